// round 1
// baseline (speedup 1.0000x reference)
#include <cuda_runtime.h>
#include <math.h>

#define NB 2
#define CC 64
#define NP 144
#define NT 2304
#define IH 96
#define IW 96
#define ID 32
#define VOLSZ (IH*IW*ID)

// 1/(2*sigma^2) with sigma = fwhm/2.355, fwhm = 128 (same for T and S)
#define INV2SIG2 ((float)(1.0/(2.0*(128.0/2.355)*(128.0/2.355))))

// ---------------- scratch (device globals; no allocation) ----------------
__device__ float g_protos[NB*NP*CC];
__device__ float g_cp[NB*NP*3];
__device__ float g_temb [NB*NT*CC];
__device__ float g_tembn[NB*NT*CC];
__device__ float g_ct[NB*NT*3];
__device__ float g_s0e[NB*NT*CC];
__device__ float g_s0c[NB*NT*3];
__device__ float g_s1e[NB*NT*CC];
__device__ float g_s1c[NB*NT*3];
__device__ float g_w  [NB*NT*NP];
__device__ float g_tgt[NB*NT*NP];
__device__ float g_acc[4];   // [s0_ce, s0_valid, s1_ce, s1_valid]

// ---------------- helpers ----------------
__device__ __forceinline__ float unnorm_reflect(float c, float size){
    float x = ((c + 1.f)*size - 1.f)*0.5f;
    float xr = fabsf(x + 0.5f);
    float extra = fmodf(xr, size);
    float flips = floorf(xr / size);
    float r = (fmodf(flips, 2.f) == 0.f) ? extra : (size - extra);
    r -= 0.5f;
    return fminf(fmaxf(r, 0.f), size - 1.f);
}

// ---------------- zero accumulators ----------------
__global__ void zero_acc_kernel(){
    int i = threadIdx.x;
    if(i < 4) g_acc[i] = 0.f;
}

// ---------------- grid sample (one block per (v,point), 64 threads=channels)
__global__ void sample_kernel(const float* __restrict__ emb,
                              const float* __restrict__ cvol,
                              const float* __restrict__ jit,
                              float* __restrict__ out_n,     // normalized emb (V,npts,64)
                              float* __restrict__ out_raw,   // raw emb or null
                              float* __restrict__ out_c,     // coords (V,npts,3)
                              int Dr, int Hr, int Wr,
                              float sd, float sh, float sw)
{
    int npts = Dr*Hr*Wr;
    int v = blockIdx.x / npts;
    int n = blockIdx.x - v*npts;
    int z = n / (Hr*Wr);
    int rem = n - z*(Hr*Wr);
    int y = rem / Wr;
    int x = rem - y*Wr;

    float tz = (jit[v*3+0] - 0.5f)*2.f*sd;
    float ty = (jit[v*3+1] - 0.5f)*2.f*sh;
    float tx = (jit[v*3+2] - 0.5f)*2.f*sw;

    float gx = ((float)x + 0.5f)*2.f/(float)Wr - 1.f + tx;
    float gy = ((float)y + 0.5f)*2.f/(float)Hr - 1.f + ty;
    float gz = ((float)z + 0.5f)*2.f/(float)Dr - 1.f + tz;

    float ux = unnorm_reflect(gx, (float)IW);
    float uy = unnorm_reflect(gy, (float)IH);
    float uz = unnorm_reflect(gz, (float)ID);

    float x0f = floorf(ux), y0f = floorf(uy), z0f = floorf(uz);
    float fx = ux - x0f, fy = uy - y0f, fz = uz - z0f;
    int x0 = (int)x0f, y0 = (int)y0f, z0 = (int)z0f;

    int xi[2] = { min(max(x0,0),IW-1), min(max(x0+1,0),IW-1) };
    int yi[2] = { min(max(y0,0),IH-1), min(max(y0+1,0),IH-1) };
    int zi[2] = { min(max(z0,0),ID-1), min(max(z0+1,0),ID-1) };
    float wxa[2] = {1.f-fx, fx};
    float wya[2] = {1.f-fy, fy};
    float wza[2] = {1.f-fz, fz};

    int c = threadIdx.x;

    // embedding gather (transposed view: (d,h,w) -> original (h,w,d))
    const float* base = emb + (size_t)(v*CC + c)*VOLSZ;
    float val = 0.f;
    #pragma unroll
    for(int dz = 0; dz < 2; dz++)
      #pragma unroll
      for(int dy = 0; dy < 2; dy++)
        #pragma unroll
        for(int dx = 0; dx < 2; dx++)
            val += wxa[dx]*wya[dy]*wza[dz] *
                   base[((size_t)yi[dy]*IW + xi[dx])*ID + zi[dz]];

    // coord gather (3 channels)
    float cval = 0.f;
    if(c < 3){
        const float* cbase = cvol + (size_t)(v*3 + c)*VOLSZ;
        #pragma unroll
        for(int dz = 0; dz < 2; dz++)
          #pragma unroll
          for(int dy = 0; dy < 2; dy++)
            #pragma unroll
            for(int dx = 0; dx < 2; dx++)
                cval += wxa[dx]*wya[dy]*wza[dz] *
                        cbase[((size_t)yi[dy]*IW + xi[dx])*ID + zi[dz]];
    }

    // block l2 norm over 64 channels
    __shared__ float ssq[64];
    ssq[c] = val*val;
    __syncthreads();
    if(c < 32) ssq[c] += ssq[c+32]; __syncthreads();
    if(c < 16) ssq[c] += ssq[c+16]; __syncthreads();
    if(c <  8) ssq[c] += ssq[c+ 8]; __syncthreads();
    if(c <  4) ssq[c] += ssq[c+ 4]; __syncthreads();
    if(c <  2) ssq[c] += ssq[c+ 2]; __syncthreads();
    if(c <  1) ssq[c] += ssq[c+ 1]; __syncthreads();
    float inv = 1.f / fmaxf(sqrtf(ssq[0]), 1e-8f);

    size_t o = (size_t)(v*npts + n)*CC + c;
    out_n[o] = val * inv;
    if(out_raw) out_raw[o] = val;
    if(c < 3) out_c[(size_t)(v*npts + n)*3 + c] = cval;
}

// ---------------- assign / targets kernel ----------------
// grid = NB * (NT/16) blocks, 256 threads. Computes softmax(sim/T) (optionally * gauss)
__global__ void assign_kernel(const float* __restrict__ tn,
                              const float* __restrict__ ct,
                              const float* __restrict__ pr,
                              const float* __restrict__ cp,
                              float* __restrict__ out,
                              int useGauss)
{
    __shared__ float sp[NP*65];   // padded stride 65 -> conflict-free dot
    __shared__ float scp[NP*3];
    __shared__ float srow[CC];
    __shared__ float sct3[3];
    __shared__ float red[256];

    int tid = threadIdx.x;
    int bpv = NT/16;
    int v  = blockIdx.x / bpv;
    int n0 = (blockIdx.x - v*bpv)*16;

    for(int i = tid; i < NP*CC; i += 256){
        int pp = i >> 6, c2 = i & 63;
        sp[pp*65 + c2] = pr[(size_t)v*NP*CC + i];
    }
    for(int i = tid; i < NP*3; i += 256) scp[i] = cp[v*NP*3 + i];
    __syncthreads();

    for(int nn = 0; nn < 16; nn++){
        int n = n0 + nn;
        if(tid < CC) srow[tid] = tn[(size_t)(v*NT + n)*CC + tid];
        if(tid < 3)  sct3[tid] = ct[(v*NT + n)*3 + tid];
        __syncthreads();

        float logit = -1e30f;
        if(tid < NP){
            float s = 0.f;
            #pragma unroll
            for(int c2 = 0; c2 < CC; c2++) s += srow[c2]*sp[tid*65 + c2];
            logit = s / 0.015f;
        }
        red[tid] = (tid < NP) ? logit : -1e30f;
        __syncthreads();
        for(int off = 128; off; off >>= 1){
            if(tid < off) red[tid] = fmaxf(red[tid], red[tid+off]);
            __syncthreads();
        }
        float mx = red[0];
        __syncthreads();

        float e = (tid < NP) ? expf(logit - mx) : 0.f;
        red[tid] = e;
        __syncthreads();
        for(int off = 128; off; off >>= 1){
            if(tid < off) red[tid] += red[tid+off];
            __syncthreads();
        }
        float den = red[0];
        __syncthreads();

        if(tid < NP){
            float a = e / den;
            if(useGauss){
                float dx = sct3[0] - scp[tid*3+0];
                float dy = sct3[1] - scp[tid*3+1];
                float dz = (sct3[2] - scp[tid*3+2])*2.f;
                a *= expf(-(dx*dx + dy*dy + dz*dz)*INV2SIG2);
            }
            out[(size_t)(v*NT + n)*NP + tid] = a;
        }
        __syncthreads();
    }
}

// ---------------- proto/coord update kernel ----------------
// grid = NB*36 blocks, 256 threads; each block owns 4 protos, thread=(psub,c)
__global__ void update_kernel(const float* __restrict__ w,
                              const float* __restrict__ temb,
                              const float* __restrict__ ct,
                              float* __restrict__ pr,
                              float* __restrict__ cp)
{
    __shared__ float srow[4*CC];
    __shared__ float sc[12];
    __shared__ float rs[256];

    int tid = threadIdx.x;
    int c  = tid & 63;
    int ps = tid >> 6;
    int v  = blockIdx.x / (NP/4);
    int p  = (blockIdx.x - v*(NP/4))*4 + ps;

    float acc = 0.f, den = 0.f, ca = 0.f;
    for(int b = 0; b < NT; b += 4){
        srow[tid] = temb[(size_t)(v*NT + b)*CC + tid];  // 4 rows coalesced
        if(tid < 12) sc[tid] = ct[(v*NT + b)*3 + tid];
        __syncthreads();
        #pragma unroll
        for(int j = 0; j < 4; j++){
            float wv = w[(size_t)(v*NT + b + j)*NP + p];   // warp-broadcast
            acc += wv * srow[j*CC + c];
            den += wv;
            if(c < 3) ca += wv * sc[j*3 + c];
        }
        __syncthreads();
    }

    float d = den + 1e-8f;
    float q = acc / d;
    rs[tid] = q*q;
    __syncthreads();
    for(int off = 32; off; off >>= 1){
        if(c < off) rs[ps*64 + c] += rs[ps*64 + c + off];
        __syncthreads();
    }
    float inv = 1.f / fmaxf(sqrtf(rs[ps*64]), 1e-8f);
    pr[(size_t)(v*NP + p)*CC + c] = q*inv;
    if(c < 3) cp[(v*NP + p)*3 + c] = ca / d;
}

// ---------------- per-student loss kernel ----------------
// grid = NB*(NT/16) blocks, 256 threads, dynamic smem: protos(pad65)+coords_t+coords_p
__global__ void loss_kernel(const float* __restrict__ se,
                            const float* __restrict__ scc,
                            const float* __restrict__ ct,
                            const float* __restrict__ cp,
                            const float* __restrict__ pr,
                            const float* __restrict__ tg,
                            int sidx)
{
    extern __shared__ float dyn[];
    float* sp  = dyn;              // NP*65
    float* sct = sp + NP*65;       // NT*3
    float* scp = sct + NT*3;       // NP*3
    __shared__ float srow[CC];
    __shared__ float rv[256];
    __shared__ int   ri[256];
    __shared__ float s3[3];

    int tid = threadIdx.x;
    int bpv = NT/16;
    int v  = blockIdx.x / bpv;
    int m0 = (blockIdx.x - v*bpv)*16;

    for(int i = tid; i < NP*CC; i += 256){
        int pp = i >> 6, c2 = i & 63;
        sp[pp*65 + c2] = pr[(size_t)v*NP*CC + i];
    }
    for(int i = tid; i < NT*3; i += 256) sct[i] = ct[(size_t)v*NT*3 + i];
    for(int i = tid; i < NP*3; i += 256) scp[i] = cp[v*NP*3 + i];
    __syncthreads();

    for(int mm = 0; mm < 16; mm++){
        int m = m0 + mm;
        if(tid < CC) srow[tid] = se[(size_t)(v*NT + m)*CC + tid];
        if(tid < 3)  s3[tid]   = scc[(v*NT + m)*3 + tid];
        __syncthreads();
        float sx = s3[0], sy = s3[1], sz = s3[2];

        // ---- argmin over teacher points ----
        float best = 1e30f; int bi = NT;
        for(int n = tid; n < NT; n += 256){
            float dx = sx - sct[n*3+0];
            float dy = sy - sct[n*3+1];
            float dz = (sz - sct[n*3+2])*2.f;
            float d2 = dx*dx + dy*dy + dz*dz;
            if(d2 < best || (d2 == best && n < bi)){ best = d2; bi = n; }
        }
        rv[tid] = best; ri[tid] = bi;
        __syncthreads();
        for(int off = 128; off; off >>= 1){
            if(tid < off){
                float ov = rv[tid+off]; int oi = ri[tid+off];
                if(ov < rv[tid] || (ov == rv[tid] && oi < ri[tid])){ rv[tid]=ov; ri[tid]=oi; }
            }
            __syncthreads();
        }
        float mind2 = rv[0];
        int   idx   = ri[0];
        __syncthreads();

        // ---- logits + pos mask ----
        float logit = -1e30f, pos = 0.f;
        if(tid < NP){
            float s = 0.f;
            #pragma unroll
            for(int c2 = 0; c2 < CC; c2++) s += srow[c2]*sp[tid*65 + c2];
            logit = s / 0.03f;
            float dx = sx - scp[tid*3+0];
            float dy = sy - scp[tid*3+1];
            float dz = (sz - scp[tid*3+2])*2.f;
            pos = (expf(-(dx*dx + dy*dy + dz*dz)*INV2SIG2) >= 0.5f) ? 1.f : 0.f;
        }

        // max
        rv[tid] = (tid < NP) ? logit : -1e30f;
        __syncthreads();
        for(int off = 128; off; off >>= 1){
            if(tid < off) rv[tid] = fmaxf(rv[tid], rv[tid+off]);
            __syncthreads();
        }
        float mx = rv[0];
        __syncthreads();
        // sum exp
        float e = (tid < NP) ? expf(logit - mx) : 0.f;
        rv[tid] = e;
        __syncthreads();
        for(int off = 128; off; off >>= 1){
            if(tid < off) rv[tid] += rv[tid+off];
            __syncthreads();
        }
        float lse = mx + logf(rv[0]);
        __syncthreads();

        // tgt = targets[idx] * pos
        float t = (tid < NP) ? tg[(size_t)(v*NT + idx)*NP + tid]*pos : 0.f;
        rv[tid] = t;
        __syncthreads();
        for(int off = 128; off; off >>= 1){
            if(tid < off) rv[tid] += rv[tid+off];
            __syncthreads();
        }
        float ts = rv[0];
        __syncthreads();

        float ctr = (tid < NP) ? t*(logit - lse) : 0.f;
        rv[tid] = ctr;
        __syncthreads();
        for(int off = 128; off; off >>= 1){
            if(tid < off) rv[tid] += rv[tid+off];
            __syncthreads();
        }
        if(tid == 0){
            float validf = (sqrtf(mind2) <= 3.0f) ? 1.f : 0.f;
            if(validf > 0.f){
                float ce = -rv[0] / (ts + 1e-8f);
                atomicAdd(&g_acc[sidx*2 + 0], ce);
                atomicAdd(&g_acc[sidx*2 + 1], 1.f);
            }
        }
        __syncthreads();
    }
}

// ---------------- finalize ----------------
__global__ void finalize_kernel(float* __restrict__ out){
    out[0] = 0.5f*( g_acc[0]/(g_acc[1] + 1e-8f) + g_acc[2]/(g_acc[3] + 1e-8f) );
}

// ---------------- host launch ----------------
extern "C" void kernel_launch(void* const* d_in, const int* in_sizes, int n_in,
                              void* d_out, int out_size)
{
    const float* e0  = (const float*)d_in[0];
    const float* e1  = (const float*)d_in[1];
    const float* et  = (const float*)d_in[2];
    const float* c0  = (const float*)d_in[3];
    const float* c1  = (const float*)d_in[4];
    const float* ctv = (const float*)d_in[5];
    // d_in[6] = frames (unused)
    const float* jp  = (const float*)d_in[7];
    const float* j0  = (const float*)d_in[8];
    const float* j1  = (const float*)d_in[9];
    const float* jt  = (const float*)d_in[10];

    float *protos, *cp, *temb, *tembn, *ct, *s0e, *s0c, *s1e, *s1c, *w, *tgt;
    cudaGetSymbolAddress((void**)&protos, g_protos);
    cudaGetSymbolAddress((void**)&cp,     g_cp);
    cudaGetSymbolAddress((void**)&temb,   g_temb);
    cudaGetSymbolAddress((void**)&tembn,  g_tembn);
    cudaGetSymbolAddress((void**)&ct,     g_ct);
    cudaGetSymbolAddress((void**)&s0e,    g_s0e);
    cudaGetSymbolAddress((void**)&s0c,    g_s0c);
    cudaGetSymbolAddress((void**)&s1e,    g_s1e);
    cudaGetSymbolAddress((void**)&s1c,    g_s1c);
    cudaGetSymbolAddress((void**)&w,      g_w);
    cudaGetSymbolAddress((void**)&tgt,    g_tgt);

    zero_acc_kernel<<<1, 32>>>();

    // protos: red_p = (4,6,6), scale = RFP/sz = (8/32, 16/96, 16/96)
    sample_kernel<<<NB*NP, 64>>>(et, ctv, jp, protos, nullptr, cp,
                                 4, 6, 6, 8.f/32.f, 16.f/96.f, 16.f/96.f);
    // reduced teacher: red = (16,12,12), scale = RF/sz = (2/32, 8/96, 8/96)
    sample_kernel<<<NB*NT, 64>>>(et, ctv, jt, tembn, temb, ct,
                                 16, 12, 12, 2.f/32.f, 8.f/96.f, 8.f/96.f);
    sample_kernel<<<NB*NT, 64>>>(e0, c0, j0, s0e, nullptr, s0c,
                                 16, 12, 12, 2.f/32.f, 8.f/96.f, 8.f/96.f);
    sample_kernel<<<NB*NT, 64>>>(e1, c1, j1, s1e, nullptr, s1c,
                                 16, 12, 12, 2.f/32.f, 8.f/96.f, 8.f/96.f);

    for(int it = 0; it < 3; it++){
        assign_kernel<<<NB*(NT/16), 256>>>(tembn, ct, protos, cp, w, 1);
        update_kernel<<<NB*(NP/4), 256>>>(w, temb, ct, protos, cp);
    }
    // targets (no gauss)
    assign_kernel<<<NB*(NT/16), 256>>>(tembn, ct, protos, cp, tgt, 0);

    size_t lsm = (size_t)(NP*65 + NT*3 + NP*3)*sizeof(float);
    static int smem_set = 0;
    if(!smem_set){
        cudaFuncSetAttribute(loss_kernel, cudaFuncAttributeMaxDynamicSharedMemorySize, (int)lsm);
        smem_set = 1;
    }
    loss_kernel<<<NB*(NT/16), 256, lsm>>>(s0e, s0c, ct, cp, protos, tgt, 0);
    loss_kernel<<<NB*(NT/16), 256, lsm>>>(s1e, s1c, ct, cp, protos, tgt, 1);

    finalize_kernel<<<1, 1>>>((float*)d_out);
}

// round 2
// speedup vs baseline: 2.7540x; 2.7540x over previous
#include <cuda_runtime.h>
#include <math.h>

#define NB 2
#define CC 64
#define NP 144
#define NT 2304
#define IH 96
#define IW 96
#define ID 32
#define VOLSZ (IH*IW*ID)
#define NCHUNK 8
#define NPER   (NT/NCHUNK)   // 288

// 1/(2*sigma^2), sigma = fwhm/2.355, fwhm = 128
#define INV2SIG2 ((float)(1.0/(2.0*(128.0/2.355)*(128.0/2.355))))

// ---------------- scratch ----------------
__device__ float g_protos[NB*NP*CC];
__device__ float g_cp[NB*NP*3];
__device__ float g_temb [NB*NT*CC];
__device__ float g_tembn[NB*NT*CC];
__device__ float g_ct[NB*NT*3];
__device__ float g_s0e[NB*NT*CC];
__device__ float g_s0c[NB*NT*3];
__device__ float g_s1e[NB*NT*CC];
__device__ float g_s1c[NB*NT*3];
__device__ float g_w  [NB*NT*NP];
__device__ float g_tgt[NB*NT*NP];
__device__ float g_part[NCHUNK*NB*NP*68];
__device__ float g_acc[4];

// ---------------- helpers ----------------
__device__ __forceinline__ float unnorm_reflect(float c, float size){
    float x = ((c + 1.f)*size - 1.f)*0.5f;
    float xr = fabsf(x + 0.5f);
    float extra = fmodf(xr, size);
    float flips = floorf(xr / size);
    float r = (fmodf(flips, 2.f) == 0.f) ? extra : (size - extra);
    r -= 0.5f;
    return fminf(fmaxf(r, 0.f), size - 1.f);
}

__device__ __forceinline__ float warpMax(float x){
    #pragma unroll
    for(int o = 16; o; o >>= 1) x = fmaxf(x, __shfl_xor_sync(0xffffffffu, x, o));
    return x;
}
__device__ __forceinline__ float warpSum(float x){
    #pragma unroll
    for(int o = 16; o; o >>= 1) x += __shfl_xor_sync(0xffffffffu, x, o);
    return x;
}

// dot of a 64-vec (held as r0,r1 across the warp) against 5 proto rows per lane.
// sp padded: 160 rows of stride 65 (rows >= NP are zero).
__device__ __forceinline__ void dot5(const float* __restrict__ sp, int lane,
                                     float r0, float r1, float lg[5]){
    const float* p0 = sp + lane*65;
    const float* p1 = p0 + 32*65;
    const float* p2 = p1 + 32*65;
    const float* p3 = p2 + 32*65;
    const float* p4 = p3 + 32*65;
    float a0=0.f,a1=0.f,a2=0.f,a3=0.f,a4=0.f;
    #pragma unroll 8
    for(int cc = 0; cc < 32; cc++){
        float vv = __shfl_sync(0xffffffffu, r0, cc);
        a0 = fmaf(vv, p0[cc], a0); a1 = fmaf(vv, p1[cc], a1);
        a2 = fmaf(vv, p2[cc], a2); a3 = fmaf(vv, p3[cc], a3);
        a4 = fmaf(vv, p4[cc], a4);
    }
    #pragma unroll 8
    for(int cc = 0; cc < 32; cc++){
        float vv = __shfl_sync(0xffffffffu, r1, cc);
        a0 = fmaf(vv, p0[32+cc], a0); a1 = fmaf(vv, p1[32+cc], a1);
        a2 = fmaf(vv, p2[32+cc], a2); a3 = fmaf(vv, p3[32+cc], a3);
        a4 = fmaf(vv, p4[32+cc], a4);
    }
    lg[0]=a0; lg[1]=a1; lg[2]=a2; lg[3]=a3; lg[4]=a4;
}

// ---------------- zero accumulators ----------------
__global__ void zero_acc_kernel(){
    int i = threadIdx.x;
    if(i < 4) g_acc[i] = 0.f;
}

// ---------------- trilinear gather core ----------------
__device__ __forceinline__ void trilerp_setup(
    int x, int y, int z, int Dr, int Hr, int Wr,
    float tx, float ty, float tz,
    int xi[2], int yi[2], int zi[2], float wx[2], float wy[2], float wz[2])
{
    float gx = ((float)x + 0.5f)*2.f/(float)Wr - 1.f + tx;
    float gy = ((float)y + 0.5f)*2.f/(float)Hr - 1.f + ty;
    float gz = ((float)z + 0.5f)*2.f/(float)Dr - 1.f + tz;
    float ux = unnorm_reflect(gx, (float)IW);
    float uy = unnorm_reflect(gy, (float)IH);
    float uz = unnorm_reflect(gz, (float)ID);
    float x0f = floorf(ux), y0f = floorf(uy), z0f = floorf(uz);
    float fx = ux-x0f, fy = uy-y0f, fz = uz-z0f;
    int x0 = (int)x0f, y0 = (int)y0f, z0 = (int)z0f;
    xi[0]=min(max(x0,0),IW-1);  xi[1]=min(max(x0+1,0),IW-1);
    yi[0]=min(max(y0,0),IH-1);  yi[1]=min(max(y0+1,0),IH-1);
    zi[0]=min(max(z0,0),ID-1);  zi[1]=min(max(z0+1,0),ID-1);
    wx[0]=1.f-fx; wx[1]=fx; wy[0]=1.f-fy; wy[1]=fy; wz[0]=1.f-fz; wz[1]=fz;
}

__device__ __forceinline__ float gather8(const float* __restrict__ base,
    const int xi[2], const int yi[2], const int zi[2],
    const float wx[2], const float wy[2], const float wz[2])
{
    float val = 0.f;
    #pragma unroll
    for(int dz=0; dz<2; dz++)
      #pragma unroll
      for(int dy=0; dy<2; dy++)
        #pragma unroll
        for(int dx=0; dx<2; dx++)
            val += wx[dx]*wy[dy]*wz[dz] *
                   base[((size_t)yi[dy]*IW + xi[dx])*ID + zi[dz]];
    return val;
}

// ---------------- proto sample (one block per (v,point), 64 thr) ----------------
__global__ void sample_proto_kernel(const float* __restrict__ emb,
                                    const float* __restrict__ cvol,
                                    const float* __restrict__ jit,
                                    float* __restrict__ out_n,
                                    float* __restrict__ out_c)
{
    const int Dr=4, Hr=6, Wr=6;
    int npts = Dr*Hr*Wr;
    int v = blockIdx.x / npts;
    int n = blockIdx.x - v*npts;
    int z = n / (Hr*Wr);
    int rem = n - z*(Hr*Wr);
    int y = rem / Wr, x = rem - y*Wr;

    float tz = (jit[v*3+0]-0.5f)*2.f*(8.f/32.f);
    float ty = (jit[v*3+1]-0.5f)*2.f*(16.f/96.f);
    float tx = (jit[v*3+2]-0.5f)*2.f*(16.f/96.f);

    int xi[2], yi[2], zi[2]; float wx[2], wy[2], wz[2];
    trilerp_setup(x,y,z,Dr,Hr,Wr,tx,ty,tz,xi,yi,zi,wx,wy,wz);

    int c = threadIdx.x;
    float val = gather8(emb + (size_t)(v*CC + c)*VOLSZ, xi,yi,zi,wx,wy,wz);
    float cval = 0.f;
    if(c < 3) cval = gather8(cvol + (size_t)(v*3 + c)*VOLSZ, xi,yi,zi,wx,wy,wz);

    __shared__ float ssq[64];
    ssq[c] = val*val;
    __syncthreads();
    if(c<32) ssq[c]+=ssq[c+32]; __syncthreads();
    if(c<16) ssq[c]+=ssq[c+16]; __syncthreads();
    if(c< 8) ssq[c]+=ssq[c+ 8]; __syncthreads();
    if(c< 4) ssq[c]+=ssq[c+ 4]; __syncthreads();
    if(c< 2) ssq[c]+=ssq[c+ 2]; __syncthreads();
    if(c< 1) ssq[c]+=ssq[c+ 1]; __syncthreads();
    float inv = 1.f / fmaxf(sqrtf(ssq[0]), 1e-8f);

    out_n[(size_t)(v*npts+n)*CC + c] = val*inv;
    if(c<3) out_c[(size_t)(v*npts+n)*3 + c] = cval;
}

// ---------------- merged big sample: grid (NB*NT/4, 3), 256 thr ----------------
struct SampleTriple {
    const float* emb[3]; const float* cv[3]; const float* jit[3];
    float* outn[3]; float* outraw[3]; float* outc[3];
};

__global__ void sample_big_kernel(SampleTriple args)
{
    const int Dr=16, Hr=12, Wr=12;
    int s  = blockIdx.y;
    int pt = threadIdx.x >> 6;
    int c  = threadIdx.x & 63;
    int gp = blockIdx.x*4 + pt;        // 0..4607
    int v  = gp / NT;
    int n  = gp - v*NT;
    int z = n / (Hr*Wr);
    int rem = n - z*(Hr*Wr);
    int y = rem / Wr, x = rem - y*Wr;

    const float* jit = args.jit[s];
    float tz = (jit[v*3+0]-0.5f)*2.f*(2.f/32.f);
    float ty = (jit[v*3+1]-0.5f)*2.f*(8.f/96.f);
    float tx = (jit[v*3+2]-0.5f)*2.f*(8.f/96.f);

    int xi[2], yi[2], zi[2]; float wx[2], wy[2], wz[2];
    trilerp_setup(x,y,z,Dr,Hr,Wr,tx,ty,tz,xi,yi,zi,wx,wy,wz);

    float val = gather8(args.emb[s] + (size_t)(v*CC + c)*VOLSZ, xi,yi,zi,wx,wy,wz);
    float cval = 0.f;
    if(c < 3) cval = gather8(args.cv[s] + (size_t)(v*3 + c)*VOLSZ, xi,yi,zi,wx,wy,wz);

    __shared__ float ssq[256];
    int t = threadIdx.x, gb = pt*64;
    ssq[t] = val*val;
    __syncthreads();
    if(c<32) ssq[t]+=ssq[t+32]; __syncthreads();
    if(c<16) ssq[t]+=ssq[t+16]; __syncthreads();
    if(c< 8) ssq[t]+=ssq[t+ 8]; __syncthreads();
    if(c< 4) ssq[t]+=ssq[t+ 4]; __syncthreads();
    if(c< 2) ssq[t]+=ssq[t+ 2]; __syncthreads();
    if(c< 1) ssq[t]+=ssq[t+ 1]; __syncthreads();
    float inv = 1.f / fmaxf(sqrtf(ssq[gb]), 1e-8f);

    size_t o = (size_t)gp*CC + c;
    args.outn[s][o] = val*inv;
    if(args.outraw[s]) args.outraw[s][o] = val;
    if(c<3) args.outc[s][(size_t)gp*3 + c] = cval;
}

// ---------------- assign: grid NB*(NT/32), 256 thr (warp-per-point×4) ----------------
__global__ void assign_kernel(const float* __restrict__ tn,
                              const float* __restrict__ ct,
                              const float* __restrict__ pr,
                              const float* __restrict__ cp,
                              float* __restrict__ out,
                              int useGauss)
{
    __shared__ float sp[160*65];
    __shared__ float scp[160*3];
    __shared__ float sct[32*3];
    int tid = threadIdx.x, lane = tid&31, wid = tid>>5;
    int v  = blockIdx.x / 72;
    int n0 = (blockIdx.x - v*72)*32;

    for(int i=tid; i<NP*CC; i+=256) sp[(i>>6)*65 + (i&63)] = pr[(size_t)v*NP*CC + i];
    for(int i=144*65+tid; i<160*65; i+=256) sp[i] = 0.f;
    for(int i=tid; i<NP*3; i+=256) scp[i] = cp[v*NP*3 + i];
    for(int i=NP*3+tid; i<160*3; i+=256) scp[i] = 0.f;
    for(int i=tid; i<96; i+=256) sct[i] = ct[((size_t)v*NT + n0)*3 + i];
    __syncthreads();

    for(int k=0; k<4; k++){
        int nl = wid*4 + k;
        size_t gn = (size_t)v*NT + n0 + nl;
        float r0 = tn[gn*64 + lane];
        float r1 = tn[gn*64 + 32 + lane];
        float lg[5];
        dot5(sp, lane, r0, r1, lg);
        bool v4 = lane < 16;
        float mx = -1e30f;
        #pragma unroll
        for(int j=0;j<5;j++){
            lg[j] *= (1.0f/0.015f);
            if(j<4 || v4) mx = fmaxf(mx, lg[j]);
        }
        mx = warpMax(mx);
        float e[5], s = 0.f;
        #pragma unroll
        for(int j=0;j<5;j++){
            e[j] = (j<4 || v4) ? expf(lg[j]-mx) : 0.f;
            s += e[j];
        }
        s = warpSum(s);
        float px = sct[nl*3], py = sct[nl*3+1], pz = sct[nl*3+2];
        #pragma unroll
        for(int j=0;j<5;j++){
            if(j==4 && !v4) continue;
            int p = lane + 32*j;
            float a = e[j]/s;
            if(useGauss){
                float dx = px - scp[p*3+0];
                float dy = py - scp[p*3+1];
                float dz = (pz - scp[p*3+2])*2.f;
                a *= expf(-(dx*dx + dy*dy + dz*dz)*INV2SIG2);
            }
            out[gn*NP + p] = a;
        }
    }
}

// ---------------- update partial: 144 blocks × 256 thr ----------------
// block = (v, chunk, pblk); warp owns 2 protos over a 288-n chunk; disjoint writes.
__global__ void update_partial_kernel(const float* __restrict__ w,
                                      const float* __restrict__ temb,
                                      const float* __restrict__ ct,
                                      float* __restrict__ part)
{
    int lane = threadIdx.x & 31, wid = threadIdx.x >> 5;
    int bx = blockIdx.x;
    int v = bx / 72;
    int r = bx - v*72;
    int chunk = r / 9;
    int pblk  = r - chunk*9;
    int p0 = (pblk*8 + wid)*2;

    size_t gn0 = (size_t)v*NT + chunk*NPER;
    const float* wr = w    + gn0*NP + p0;
    const float* tr = temb + gn0*64;
    const float* cr = ct   + gn0*3;

    float a00=0.f,a01=0.f,a10=0.f,a11=0.f,d0=0.f,d1=0.f,c0=0.f,c1=0.f;
    for(int i=0;i<NPER;i++){
        float w0 = wr[0], w1 = wr[1];
        float t0 = tr[lane], t1 = tr[32+lane];
        a00 = fmaf(w0,t0,a00); a01 = fmaf(w0,t1,a01);
        a10 = fmaf(w1,t0,a10); a11 = fmaf(w1,t1,a11);
        d0 += w0; d1 += w1;
        if(lane<3){ float cc = cr[lane]; c0 = fmaf(w0,cc,c0); c1 = fmaf(w1,cc,c1); }
        wr += NP; tr += 64; cr += 3;
    }
    size_t b0 = ((size_t)(chunk*NB + v)*NP + p0)*68;
    part[b0+lane]    = a00;
    part[b0+32+lane] = a01;
    if(lane==0) part[b0+64] = d0;
    if(lane<3)  part[b0+65+lane] = c0;
    size_t b1 = b0 + 68;
    part[b1+lane]    = a10;
    part[b1+32+lane] = a11;
    if(lane==0) part[b1+64] = d1;
    if(lane<3)  part[b1+65+lane] = c1;
}

// ---------------- normalize: 36 blocks × 256 thr (warp per (v,p)) ----------------
__global__ void normalize_kernel(const float* __restrict__ part,
                                 float* __restrict__ pr,
                                 float* __restrict__ cp)
{
    int lane = threadIdx.x & 31, wid = threadIdx.x >> 5;
    int gw = blockIdx.x*8 + wid;        // 0..287
    int v = gw / NP, p = gw - v*NP;

    float a0=0.f, a1=0.f, den=0.f, ca=0.f;
    #pragma unroll
    for(int ch=0; ch<NCHUNK; ch++){
        size_t b = ((size_t)(ch*NB + v)*NP + p)*68;
        a0  += part[b+lane];
        a1  += part[b+32+lane];
        den += part[b+64];
        if(lane<3) ca += part[b+65+lane];
    }
    float d = den + 1e-8f;
    float q0 = a0/d, q1 = a1/d;
    float ss = warpSum(q0*q0 + q1*q1);
    float inv = 1.f / fmaxf(sqrtf(ss), 1e-8f);
    pr[(size_t)(v*NP+p)*64 + lane]      = q0*inv;
    pr[(size_t)(v*NP+p)*64 + 32 + lane] = q1*inv;
    if(lane<3) cp[(v*NP+p)*3 + lane] = ca/d;
}

// ---------------- loss: grid (NB*(NT/32), 2), 256 thr, dyn smem ----------------
__global__ void loss_kernel(const float* __restrict__ se0, const float* __restrict__ sc0,
                            const float* __restrict__ se1, const float* __restrict__ sc1,
                            const float* __restrict__ ct,  const float* __restrict__ cp,
                            const float* __restrict__ pr,  const float* __restrict__ tg)
{
    extern __shared__ float dyn[];
    float* sp  = dyn;              // 160*65
    float* sct = sp + 160*65;      // NT*3
    float* scp = sct + NT*3;       // 160*3
    __shared__ float bacc[2];

    int sidx = blockIdx.y;
    const float* se  = sidx ? se1 : se0;
    const float* scc = sidx ? sc1 : sc0;
    int tid = threadIdx.x, lane = tid&31, wid = tid>>5;
    int v  = blockIdx.x / 72;
    int m0 = (blockIdx.x - v*72)*32;

    if(tid < 2) bacc[tid] = 0.f;
    for(int i=tid; i<NP*CC; i+=256) sp[(i>>6)*65 + (i&63)] = pr[(size_t)v*NP*CC + i];
    for(int i=144*65+tid; i<160*65; i+=256) sp[i] = 0.f;
    for(int i=tid; i<NT*3; i+=256) sct[i] = ct[(size_t)v*NT*3 + i];
    for(int i=tid; i<NP*3; i+=256) scp[i] = cp[v*NP*3 + i];
    for(int i=NP*3+tid; i<160*3; i+=256) scp[i] = 0.f;
    __syncthreads();

    for(int k=0; k<4; k++){
        int ml = wid*4 + k;
        size_t gm = (size_t)v*NT + m0 + ml;
        float r0 = se[gm*64 + lane];
        float r1 = se[gm*64 + 32 + lane];
        float sx = scc[gm*3+0], sy = scc[gm*3+1], sz = scc[gm*3+2];

        // argmin over teacher points (first-min index semantics)
        float best = 1e30f; int bi = NT;
        for(int nn=lane; nn<NT; nn+=32){
            float dx = sx - sct[nn*3+0];
            float dy = sy - sct[nn*3+1];
            float dz = (sz - sct[nn*3+2])*2.f;
            float d2 = fmaf(dx,dx, fmaf(dy,dy, dz*dz));
            if(d2 < best){ best = d2; bi = nn; }
        }
        #pragma unroll
        for(int o=16;o;o>>=1){
            float ov = __shfl_xor_sync(0xffffffffu, best, o);
            int   oi = __shfl_xor_sync(0xffffffffu, bi, o);
            if(ov < best || (ov == best && oi < bi)){ best = ov; bi = oi; }
        }

        float lg[5];
        dot5(sp, lane, r0, r1, lg);
        bool v4 = lane < 16;
        float mx = -1e30f;
        #pragma unroll
        for(int j=0;j<5;j++){
            lg[j] *= (1.0f/0.03f);
            if(j<4 || v4) mx = fmaxf(mx, lg[j]);
        }
        mx = warpMax(mx);
        float s = 0.f;
        #pragma unroll
        for(int j=0;j<5;j++) s += (j<4 || v4) ? expf(lg[j]-mx) : 0.f;
        s = warpSum(s);
        float lse = mx + logf(s);

        const float* tgrow = tg + ((size_t)v*NT + bi)*NP;
        float ts = 0.f, ctr = 0.f;
        #pragma unroll
        for(int j=0;j<5;j++){
            if(j==4 && !v4) continue;
            int p = lane + 32*j;
            float dx = sx - scp[p*3+0];
            float dy = sy - scp[p*3+1];
            float dz = (sz - scp[p*3+2])*2.f;
            float pos = (expf(-(dx*dx + dy*dy + dz*dz)*INV2SIG2) >= 0.5f) ? 1.f : 0.f;
            float t = tgrow[p]*pos;
            ts  += t;
            ctr += t*(lg[j]-lse);
        }
        ts  = warpSum(ts);
        ctr = warpSum(ctr);
        if(lane==0 && sqrtf(best) <= 3.0f){
            atomicAdd(&bacc[0], -ctr/(ts + 1e-8f));
            atomicAdd(&bacc[1], 1.f);
        }
    }
    __syncthreads();
    if(tid==0){
        atomicAdd(&g_acc[sidx*2+0], bacc[0]);
        atomicAdd(&g_acc[sidx*2+1], bacc[1]);
    }
}

// ---------------- finalize ----------------
__global__ void finalize_kernel(float* __restrict__ out){
    out[0] = 0.5f*( g_acc[0]/(g_acc[1] + 1e-8f) + g_acc[2]/(g_acc[3] + 1e-8f) );
}

// ---------------- host launch ----------------
extern "C" void kernel_launch(void* const* d_in, const int* in_sizes, int n_in,
                              void* d_out, int out_size)
{
    const float* e0  = (const float*)d_in[0];
    const float* e1  = (const float*)d_in[1];
    const float* et  = (const float*)d_in[2];
    const float* c0  = (const float*)d_in[3];
    const float* c1  = (const float*)d_in[4];
    const float* ctv = (const float*)d_in[5];
    const float* jp  = (const float*)d_in[7];
    const float* j0  = (const float*)d_in[8];
    const float* j1  = (const float*)d_in[9];
    const float* jt  = (const float*)d_in[10];

    float *protos,*cp,*temb,*tembn,*ct,*s0e,*s0c,*s1e,*s1c,*w,*tgt,*part;
    cudaGetSymbolAddress((void**)&protos, g_protos);
    cudaGetSymbolAddress((void**)&cp,     g_cp);
    cudaGetSymbolAddress((void**)&temb,   g_temb);
    cudaGetSymbolAddress((void**)&tembn,  g_tembn);
    cudaGetSymbolAddress((void**)&ct,     g_ct);
    cudaGetSymbolAddress((void**)&s0e,    g_s0e);
    cudaGetSymbolAddress((void**)&s0c,    g_s0c);
    cudaGetSymbolAddress((void**)&s1e,    g_s1e);
    cudaGetSymbolAddress((void**)&s1c,    g_s1c);
    cudaGetSymbolAddress((void**)&w,      g_w);
    cudaGetSymbolAddress((void**)&tgt,    g_tgt);
    cudaGetSymbolAddress((void**)&part,   g_part);

    zero_acc_kernel<<<1, 32>>>();

    sample_proto_kernel<<<NB*NP, 64>>>(et, ctv, jp, protos, cp);

    SampleTriple args;
    args.emb[0]=et;  args.emb[1]=e0;  args.emb[2]=e1;
    args.cv[0]=ctv;  args.cv[1]=c0;   args.cv[2]=c1;
    args.jit[0]=jt;  args.jit[1]=j0;  args.jit[2]=j1;
    args.outn[0]=tembn; args.outn[1]=s0e; args.outn[2]=s1e;
    args.outraw[0]=temb; args.outraw[1]=nullptr; args.outraw[2]=nullptr;
    args.outc[0]=ct; args.outc[1]=s0c; args.outc[2]=s1c;
    sample_big_kernel<<<dim3(NB*NT/4, 3), 256>>>(args);

    for(int it=0; it<3; it++){
        assign_kernel<<<NB*(NT/32), 256>>>(tembn, ct, protos, cp, w, 1);
        update_partial_kernel<<<NB*NCHUNK*9, 256>>>(w, temb, ct, part);
        normalize_kernel<<<36, 256>>>(part, protos, cp);
    }
    assign_kernel<<<NB*(NT/32), 256>>>(tembn, ct, protos, cp, tgt, 0);

    size_t lsm = (size_t)(160*65 + NT*3 + 160*3)*sizeof(float);
    cudaFuncSetAttribute(loss_kernel, cudaFuncAttributeMaxDynamicSharedMemorySize, (int)lsm);
    loss_kernel<<<dim3(NB*(NT/32), 2), 256, lsm>>>(s0e, s0c, s1e, s1c, ct, cp, protos, tgt);

    finalize_kernel<<<1, 1>>>((float*)d_out);
}

// round 3
// speedup vs baseline: 4.8666x; 1.7671x over previous
#include <cuda_runtime.h>
#include <math.h>

#define NB 2
#define CC 64
#define NP 144
#define NT 2304
#define IH 96
#define IW 96
#define ID 32
#define VOLSZ (IH*IW*ID)
#define NCHUNK 16
#define NPER   (NT/NCHUNK)   // 144
#define PS 161               // padded stride of transposed proto smem [cc][p]

#define INV2SIG2 ((float)(1.0/(2.0*(128.0/2.355)*(128.0/2.355))))

// ---------------- scratch ----------------
__device__ float g_protos[NB*NP*CC];
__device__ float g_cp[NB*NP*3];
__device__ float g_temb [NB*NT*CC];
__device__ float g_tembn[NB*NT*CC];
__device__ float g_ct[NB*NT*3];
__device__ float g_s0e[NB*NT*CC];
__device__ float g_s0c[NB*NT*3];
__device__ float g_s1e[NB*NT*CC];
__device__ float g_s1c[NB*NT*3];
__device__ float g_w  [NB*NT*NP];
__device__ float g_tgt[NB*NT*NP];
__device__ float g_part[NCHUNK*NB*NP*68];
__device__ float g_acc[4];

// ---------------- helpers ----------------
__device__ __forceinline__ float unnorm_reflect(float c, float size){
    float x = ((c + 1.f)*size - 1.f)*0.5f;
    float xr = fabsf(x + 0.5f);
    float extra = fmodf(xr, size);
    float flips = floorf(xr / size);
    float r = (fmodf(flips, 2.f) == 0.f) ? extra : (size - extra);
    r -= 0.5f;
    return fminf(fmaxf(r, 0.f), size - 1.f);
}
__device__ __forceinline__ float warpMax(float x){
    #pragma unroll
    for(int o=16;o;o>>=1) x = fmaxf(x, __shfl_xor_sync(0xffffffffu, x, o));
    return x;
}
__device__ __forceinline__ float warpSum(float x){
    #pragma unroll
    for(int o=16;o;o>>=1) x += __shfl_xor_sync(0xffffffffu, x, o);
    return x;
}

__device__ __forceinline__ void trilerp_setup2(
    int x, int y, int z, int Dr, int Hr, int Wr,
    float tx, float ty, float tz,
    int xi[2], int yi[2], int zi[2], float wx[2], float wy[2], float wz[2],
    float* ux_o, float* uy_o, float* uz_o)
{
    float gx = ((float)x + 0.5f)*2.f/(float)Wr - 1.f + tx;
    float gy = ((float)y + 0.5f)*2.f/(float)Hr - 1.f + ty;
    float gz = ((float)z + 0.5f)*2.f/(float)Dr - 1.f + tz;
    float ux = unnorm_reflect(gx, (float)IW);
    float uy = unnorm_reflect(gy, (float)IH);
    float uz = unnorm_reflect(gz, (float)ID);
    float x0f = floorf(ux), y0f = floorf(uy), z0f = floorf(uz);
    float fx = ux-x0f, fy = uy-y0f, fz = uz-z0f;
    int x0=(int)x0f, y0=(int)y0f, z0=(int)z0f;
    xi[0]=min(max(x0,0),IW-1);  xi[1]=min(max(x0+1,0),IW-1);
    yi[0]=min(max(y0,0),IH-1);  yi[1]=min(max(y0+1,0),IH-1);
    zi[0]=min(max(z0,0),ID-1);  zi[1]=min(max(z0+1,0),ID-1);
    wx[0]=1.f-fx; wx[1]=fx; wy[0]=1.f-fy; wy[1]=fy; wz[0]=1.f-fz; wz[1]=fz;
    *ux_o=ux; *uy_o=uy; *uz_o=uz;
}

__device__ __forceinline__ float gather8(const float* __restrict__ base,
    const int xi[2], const int yi[2], const int zi[2],
    const float wx[2], const float wy[2], const float wz[2])
{
    float val = 0.f;
    #pragma unroll
    for(int dz=0; dz<2; dz++)
      #pragma unroll
      for(int dy=0; dy<2; dy++)
        #pragma unroll
        for(int dx=0; dx<2; dx++)
            val += wx[dx]*wy[dy]*wz[dz] *
                   base[((size_t)yi[dy]*IW + xi[dx])*ID + zi[dz]];
    return val;
}

// ---------------- merged sampling: grid (1152, 4), 256 thr ----------------
struct SampleArgs {
    const float* emb[3]; const float* jit[3];
    float* outn[3]; float* outraw[3]; float* outc[3];
    const float* pemb; const float* pjit;
    float* pout; float* pcoord;
};

__global__ void sample_all_kernel(SampleArgs a)
{
    int s = blockIdx.y;
    int pt = threadIdx.x >> 6;
    int c  = threadIdx.x & 63;
    const float *emb, *jit;
    float *outn, *outraw, *outc;
    int gp, v, n, Dr, Hr, Wr; float sd, sh, sw_;
    if(s < 3){
        gp = blockIdx.x*4 + pt; v = gp/NT; n = gp - v*NT;
        Dr=16; Hr=12; Wr=12; sd=2.f/32.f; sh=8.f/96.f; sw_=8.f/96.f;
        emb=a.emb[s]; jit=a.jit[s]; outn=a.outn[s]; outraw=a.outraw[s]; outc=a.outc[s];
    } else {
        if(blockIdx.x >= 72) return;
        if(blockIdx.x==0 && threadIdx.x < 4) g_acc[threadIdx.x] = 0.f;
        gp = blockIdx.x*4 + pt; v = gp/NP; n = gp - v*NP;
        Dr=4; Hr=6; Wr=6; sd=8.f/32.f; sh=16.f/96.f; sw_=16.f/96.f;
        emb=a.pemb; jit=a.pjit; outn=a.pout; outraw=nullptr; outc=a.pcoord;
    }
    int HW = Hr*Wr;
    int z = n/HW; int rem = n - z*HW; int yy = rem/Wr; int xx = rem - yy*Wr;
    float tz = (jit[v*3+0]-0.5f)*2.f*sd;
    float ty = (jit[v*3+1]-0.5f)*2.f*sh;
    float tx = (jit[v*3+2]-0.5f)*2.f*sw_;

    int xi[2], yi[2], zi[2]; float wx[2], wy[2], wz[2], ux, uy, uz;
    trilerp_setup2(xx,yy,z,Dr,Hr,Wr,tx,ty,tz,xi,yi,zi,wx,wy,wz,&ux,&uy,&uz);

    float val = gather8(emb + (size_t)(v*CC + c)*VOLSZ, xi,yi,zi,wx,wy,wz);

    __shared__ float ssq[256];
    int t = threadIdx.x, gb = pt*64;
    ssq[t] = val*val;
    __syncthreads();
    if(c<32) ssq[t]+=ssq[t+32]; __syncthreads();
    if(c<16) ssq[t]+=ssq[t+16]; __syncthreads();
    if(c< 8) ssq[t]+=ssq[t+ 8]; __syncthreads();
    if(c< 4) ssq[t]+=ssq[t+ 4]; __syncthreads();
    if(c< 2) ssq[t]+=ssq[t+ 2]; __syncthreads();
    if(c< 1) ssq[t]+=ssq[t+ 1]; __syncthreads();
    float inv = 1.f / fmaxf(sqrtf(ssq[gb]), 1e-8f);

    size_t o = (size_t)gp*CC + c;
    outn[o] = val*inv;
    if(outraw) outraw[o] = val;
    // coord field is a meshgrid: trilerp of it = the clamped/reflected coordinate
    if(c==0){
        outc[(size_t)gp*3 + 0] = uy;   // channel0 = h
        outc[(size_t)gp*3 + 1] = ux;   // channel1 = w
        outc[(size_t)gp*3 + 2] = uz;   // channel2 = d
    }
}

// ---------------- assign: grid 288, block 128; warp = 4 points simultaneously ----
__global__ void assign_kernel(const float* __restrict__ tn,
                              const float* __restrict__ ct,
                              const float* __restrict__ pr,
                              const float* __restrict__ cp,
                              float* __restrict__ out,
                              int useGauss)
{
    __shared__ float spT[64*PS];
    __shared__ float scpx[160], scpy[160], scpz[160];
    int tid = threadIdx.x, lane = tid&31, wid = tid>>5;
    int v  = blockIdx.x / (NT/16);
    int n0 = (blockIdx.x - v*(NT/16))*16;

    for(int i=tid; i<NP*CC; i+=128){
        int p = i>>6, cc2 = i&63;
        spT[cc2*PS + p] = pr[(size_t)v*NP*CC + i];
    }
    for(int i=tid; i<64*(PS-NP); i+=128){
        int cc2 = i/(PS-NP), p = NP + i%(PS-NP);
        spT[cc2*PS + p] = 0.f;
    }
    for(int i=tid; i<160; i+=128){
        float x=0.f, yv=0.f, z=0.f;
        if(i<NP){ x=cp[(v*NP+i)*3+0]; yv=cp[(v*NP+i)*3+1]; z=cp[(v*NP+i)*3+2]; }
        scpx[i]=x; scpy[i]=yv; scpz[i]=z;
    }
    __syncthreads();

    size_t gnb = (size_t)v*NT + n0 + wid*4;
    float r[2][4], px[4], py[4], pz[4];
    #pragma unroll
    for(int q=0;q<4;q++){
        r[0][q] = tn[(gnb+q)*64 + lane];
        r[1][q] = tn[(gnb+q)*64 + 32 + lane];
        px[q] = ct[(gnb+q)*3+0]; py[q] = ct[(gnb+q)*3+1]; pz[q] = ct[(gnb+q)*3+2];
    }

    float acc[4][5];
    #pragma unroll
    for(int q=0;q<4;q++){
        #pragma unroll
        for(int j=0;j<5;j++) acc[q][j]=0.f;
    }
    #pragma unroll
    for(int h=0;h<2;h++){
        #pragma unroll 8
        for(int cc2=0; cc2<32; cc2++){
            const float* row = spT + (h*32+cc2)*PS + lane;
            float p0=row[0], p1=row[32], p2=row[64], p3=row[96], p4=row[128];
            #pragma unroll
            for(int q=0;q<4;q++){
                float vv = __shfl_sync(0xffffffffu, r[h][q], cc2);
                acc[q][0]=fmaf(vv,p0,acc[q][0]);
                acc[q][1]=fmaf(vv,p1,acc[q][1]);
                acc[q][2]=fmaf(vv,p2,acc[q][2]);
                acc[q][3]=fmaf(vv,p3,acc[q][3]);
                acc[q][4]=fmaf(vv,p4,acc[q][4]);
            }
        }
    }

    bool v4 = lane < 16;
    #pragma unroll
    for(int q=0;q<4;q++){
        float lg[5], mx = -1e30f;
        #pragma unroll
        for(int j=0;j<5;j++){
            lg[j] = acc[q][j]*(1.f/0.015f);
            if(j<4 || v4) mx = fmaxf(mx, lg[j]);
        }
        mx = warpMax(mx);
        float e[5], sum = 0.f;
        #pragma unroll
        for(int j=0;j<5;j++){ e[j] = (j<4||v4) ? expf(lg[j]-mx) : 0.f; sum += e[j]; }
        sum = warpSum(sum);
        float invs = 1.f/sum;
        #pragma unroll
        for(int j=0;j<5;j++){
            if(j==4 && !v4) continue;
            int p = lane + 32*j;
            float aa = e[j]*invs;
            if(useGauss){
                float dx = px[q]-scpx[p];
                float dy = py[q]-scpy[p];
                float dz = (pz[q]-scpz[p])*2.f;
                aa *= expf(-(dx*dx+dy*dy+dz*dz)*INV2SIG2);
            }
            out[(gnb+q)*NP + p] = aa;
        }
    }
}

// ---------------- update partial: grid 288, 256 thr, dyn smem ----------------
__global__ void update_partial_kernel(const float* __restrict__ w,
                                      const float* __restrict__ temb,
                                      const float* __restrict__ ct,
                                      float* __restrict__ part)
{
    extern __shared__ float us[];
    float* sw_ = us;              // NPER*16
    float* st  = us + NPER*16;    // NPER*64
    float* sc  = st + NPER*64;    // NPER*3

    int tid = threadIdx.x, lane = tid&31, wp = tid>>5;
    int bx = blockIdx.x;
    int v = bx / (9*NCHUNK);
    int rr = bx - v*(9*NCHUNK);
    int ch = rr / 9, pblk = rr - ch*9;
    int p0b = pblk*16;
    size_t gn0 = (size_t)v*NT + ch*NPER;

    for(int i=tid; i<NPER*16; i+=256){
        int n = i>>4, pj = i&15;
        sw_[i] = w[(gn0+n)*NP + p0b + pj];
    }
    {
        const float4* src = (const float4*)(temb + gn0*64);
        float4* dst = (float4*)st;
        for(int i=tid; i<NPER*16; i+=256) dst[i] = src[i];
    }
    for(int i=tid; i<NPER*3; i+=256) sc[i] = ct[gn0*3 + i];
    __syncthreads();

    int wp2 = wp*2;
    float a00=0.f,a01=0.f,a10=0.f,a11=0.f,d0=0.f,d1=0.f,c0a=0.f,c1a=0.f;
    #pragma unroll 4
    for(int n=0;n<NPER;n++){
        float w0 = sw_[n*16+wp2], w1 = sw_[n*16+wp2+1];
        float t0 = st[n*64+lane], t1 = st[n*64+32+lane];
        a00 = fmaf(w0,t0,a00); a01 = fmaf(w0,t1,a01);
        a10 = fmaf(w1,t0,a10); a11 = fmaf(w1,t1,a11);
        d0 += w0; d1 += w1;
        if(lane<3){ float cv = sc[n*3+lane]; c0a = fmaf(w0,cv,c0a); c1a = fmaf(w1,cv,c1a); }
    }
    int p = p0b + wp2;
    size_t b0 = ((size_t)(ch*NB + v)*NP + p)*68;
    part[b0+lane]    = a00;
    part[b0+32+lane] = a01;
    if(lane==0) part[b0+64] = d0;
    if(lane<3)  part[b0+65+lane] = c0a;
    size_t b1 = b0 + 68;
    part[b1+lane]    = a10;
    part[b1+32+lane] = a11;
    if(lane==0) part[b1+64] = d1;
    if(lane<3)  part[b1+65+lane] = c1a;
}

// ---------------- normalize: 36 blocks × 256 (warp per (v,p)) ----------------
__global__ void normalize_kernel(const float* __restrict__ part,
                                 float* __restrict__ pr,
                                 float* __restrict__ cp)
{
    int lane = threadIdx.x & 31, wid = threadIdx.x >> 5;
    int gw = blockIdx.x*8 + wid;
    int v = gw / NP, p = gw - v*NP;

    float a0=0.f, a1=0.f, den=0.f, ca=0.f;
    #pragma unroll
    for(int ch=0; ch<NCHUNK; ch++){
        size_t b = ((size_t)(ch*NB + v)*NP + p)*68;
        a0  += part[b+lane];
        a1  += part[b+32+lane];
        den += part[b+64];
        if(lane<3) ca += part[b+65+lane];
    }
    float d = den + 1e-8f;
    float q0 = a0/d, q1 = a1/d;
    float ss = warpSum(q0*q0 + q1*q1);
    float inv = 1.f / fmaxf(sqrtf(ss), 1e-8f);
    pr[(size_t)(v*NP+p)*64 + lane]      = q0*inv;
    pr[(size_t)(v*NP+p)*64 + 32 + lane] = q1*inv;
    if(lane<3) cp[(v*NP+p)*3 + lane] = ca/d;
}

// ---------------- loss: grid (288,2), block 128, dyn smem ----------------
__global__ void loss_kernel(const float* __restrict__ se0, const float* __restrict__ sc0,
                            const float* __restrict__ se1, const float* __restrict__ sc1,
                            const float* __restrict__ ct,  const float* __restrict__ cp,
                            const float* __restrict__ pr,  const float* __restrict__ tg)
{
    extern __shared__ float dyn[];
    float* spT  = dyn;               // 64*PS
    float* sctx = spT + 64*PS;       // NT
    float* scty = sctx + NT;         // NT
    float* sctz = scty + NT;         // NT
    float* scpx = sctz + NT;         // 160
    float* scpy = scpx + 160;
    float* scpz = scpy + 160;
    __shared__ float bacc[2];

    int sidx = blockIdx.y;
    const float* se  = sidx ? se1 : se0;
    const float* scc = sidx ? sc1 : sc0;
    int tid = threadIdx.x, lane = tid&31, wid = tid>>5;
    int v  = blockIdx.x / (NT/16);
    int m0 = (blockIdx.x - v*(NT/16))*16;

    if(tid < 2) bacc[tid] = 0.f;
    for(int i=tid; i<NP*CC; i+=128){
        int p = i>>6, cc2 = i&63;
        spT[cc2*PS + p] = pr[(size_t)v*NP*CC + i];
    }
    for(int i=tid; i<64*(PS-NP); i+=128){
        int cc2 = i/(PS-NP), p = NP + i%(PS-NP);
        spT[cc2*PS + p] = 0.f;
    }
    for(int i=tid; i<NT; i+=128){
        sctx[i] = ct[((size_t)v*NT + i)*3 + 0];
        scty[i] = ct[((size_t)v*NT + i)*3 + 1];
        sctz[i] = ct[((size_t)v*NT + i)*3 + 2];
    }
    for(int i=tid; i<160; i+=128){
        float x=0.f, yv=0.f, z=0.f;
        if(i<NP){ x=cp[(v*NP+i)*3+0]; yv=cp[(v*NP+i)*3+1]; z=cp[(v*NP+i)*3+2]; }
        scpx[i]=x; scpy[i]=yv; scpz[i]=z;
    }
    __syncthreads();

    size_t gmb = (size_t)v*NT + m0 + wid*4;
    float r[2][4], sx[4], sy[4], sz[4];
    #pragma unroll
    for(int q=0;q<4;q++){
        r[0][q] = se[(gmb+q)*64 + lane];
        r[1][q] = se[(gmb+q)*64 + 32 + lane];
        sx[q] = scc[(gmb+q)*3+0]; sy[q] = scc[(gmb+q)*3+1]; sz[q] = scc[(gmb+q)*3+2];
    }

    // 4-way argmin over teacher points (SoA, conflict-free)
    float best[4] = {1e30f,1e30f,1e30f,1e30f};
    int   bi[4]   = {NT,NT,NT,NT};
    for(int nn=lane; nn<NT; nn+=32){
        float tx = sctx[nn], ty = scty[nn], tz = sctz[nn];
        #pragma unroll
        for(int q=0;q<4;q++){
            float dx = sx[q]-tx, dy = sy[q]-ty, dz = (sz[q]-tz)*2.f;
            float d2 = fmaf(dx,dx, fmaf(dy,dy, dz*dz));
            if(d2 < best[q]){ best[q] = d2; bi[q] = nn; }
        }
    }
    #pragma unroll
    for(int q=0;q<4;q++){
        #pragma unroll
        for(int o=16;o;o>>=1){
            float ov = __shfl_xor_sync(0xffffffffu, best[q], o);
            int   oi = __shfl_xor_sync(0xffffffffu, bi[q], o);
            if(ov < best[q] || (ov == best[q] && oi < bi[q])){ best[q]=ov; bi[q]=oi; }
        }
    }

    // 4-way dot against protos
    float acc[4][5];
    #pragma unroll
    for(int q=0;q<4;q++){
        #pragma unroll
        for(int j=0;j<5;j++) acc[q][j]=0.f;
    }
    #pragma unroll
    for(int h=0;h<2;h++){
        #pragma unroll 8
        for(int cc2=0; cc2<32; cc2++){
            const float* row = spT + (h*32+cc2)*PS + lane;
            float p0=row[0], p1=row[32], p2=row[64], p3=row[96], p4=row[128];
            #pragma unroll
            for(int q=0;q<4;q++){
                float vv = __shfl_sync(0xffffffffu, r[h][q], cc2);
                acc[q][0]=fmaf(vv,p0,acc[q][0]);
                acc[q][1]=fmaf(vv,p1,acc[q][1]);
                acc[q][2]=fmaf(vv,p2,acc[q][2]);
                acc[q][3]=fmaf(vv,p3,acc[q][3]);
                acc[q][4]=fmaf(vv,p4,acc[q][4]);
            }
        }
    }

    bool v4 = lane < 16;
    #pragma unroll
    for(int q=0;q<4;q++){
        float lg[5], mx = -1e30f;
        #pragma unroll
        for(int j=0;j<5;j++){
            lg[j] = acc[q][j]*(1.f/0.03f);
            if(j<4 || v4) mx = fmaxf(mx, lg[j]);
        }
        mx = warpMax(mx);
        float sum = 0.f;
        #pragma unroll
        for(int j=0;j<5;j++) sum += (j<4||v4) ? expf(lg[j]-mx) : 0.f;
        sum = warpSum(sum);
        float lse = mx + logf(sum);

        const float* tgrow = tg + ((size_t)v*NT + bi[q])*NP;
        float ts = 0.f, ctr = 0.f;
        #pragma unroll
        for(int j=0;j<5;j++){
            if(j==4 && !v4) continue;
            int p = lane + 32*j;
            float dx = sx[q]-scpx[p];
            float dy = sy[q]-scpy[p];
            float dz = (sz[q]-scpz[p])*2.f;
            float pos = (expf(-(dx*dx+dy*dy+dz*dz)*INV2SIG2) >= 0.5f) ? 1.f : 0.f;
            float t = tgrow[p]*pos;
            ts  += t;
            ctr += t*(lg[j]-lse);
        }
        ts  = warpSum(ts);
        ctr = warpSum(ctr);
        if(lane==0 && sqrtf(best[q]) <= 3.0f){
            atomicAdd(&bacc[0], -ctr/(ts + 1e-8f));
            atomicAdd(&bacc[1], 1.f);
        }
    }
    __syncthreads();
    if(tid==0){
        atomicAdd(&g_acc[sidx*2+0], bacc[0]);
        atomicAdd(&g_acc[sidx*2+1], bacc[1]);
    }
}

// ---------------- finalize ----------------
__global__ void finalize_kernel(float* __restrict__ out){
    out[0] = 0.5f*( g_acc[0]/(g_acc[1] + 1e-8f) + g_acc[2]/(g_acc[3] + 1e-8f) );
}

// ---------------- host launch ----------------
extern "C" void kernel_launch(void* const* d_in, const int* in_sizes, int n_in,
                              void* d_out, int out_size)
{
    const float* e0  = (const float*)d_in[0];
    const float* e1  = (const float*)d_in[1];
    const float* et  = (const float*)d_in[2];
    const float* jp  = (const float*)d_in[7];
    const float* j0  = (const float*)d_in[8];
    const float* j1  = (const float*)d_in[9];
    const float* jt  = (const float*)d_in[10];

    float *protos,*cp,*temb,*tembn,*ct,*s0e,*s0c,*s1e,*s1c,*w,*tgt,*part;
    cudaGetSymbolAddress((void**)&protos, g_protos);
    cudaGetSymbolAddress((void**)&cp,     g_cp);
    cudaGetSymbolAddress((void**)&temb,   g_temb);
    cudaGetSymbolAddress((void**)&tembn,  g_tembn);
    cudaGetSymbolAddress((void**)&ct,     g_ct);
    cudaGetSymbolAddress((void**)&s0e,    g_s0e);
    cudaGetSymbolAddress((void**)&s0c,    g_s0c);
    cudaGetSymbolAddress((void**)&s1e,    g_s1e);
    cudaGetSymbolAddress((void**)&s1c,    g_s1c);
    cudaGetSymbolAddress((void**)&w,      g_w);
    cudaGetSymbolAddress((void**)&tgt,    g_tgt);
    cudaGetSymbolAddress((void**)&part,   g_part);

    size_t usm = (size_t)(NPER*16 + NPER*64 + NPER*3)*sizeof(float);
    size_t lsm = (size_t)(64*PS + 3*NT + 3*160)*sizeof(float);
    cudaFuncSetAttribute(update_partial_kernel, cudaFuncAttributeMaxDynamicSharedMemorySize, (int)usm);
    cudaFuncSetAttribute(loss_kernel, cudaFuncAttributeMaxDynamicSharedMemorySize, (int)lsm);

    SampleArgs a;
    a.emb[0]=et;  a.emb[1]=e0;  a.emb[2]=e1;
    a.jit[0]=jt;  a.jit[1]=j0;  a.jit[2]=j1;
    a.outn[0]=tembn; a.outn[1]=s0e; a.outn[2]=s1e;
    a.outraw[0]=temb; a.outraw[1]=nullptr; a.outraw[2]=nullptr;
    a.outc[0]=ct; a.outc[1]=s0c; a.outc[2]=s1c;
    a.pemb=et; a.pjit=jp; a.pout=protos; a.pcoord=cp;
    sample_all_kernel<<<dim3(NB*NT/4, 4), 256>>>(a);

    for(int it=0; it<3; it++){
        assign_kernel<<<NB*(NT/16), 128>>>(tembn, ct, protos, cp, w, 1);
        update_partial_kernel<<<NB*9*NCHUNK, 256, usm>>>(w, temb, ct, part);
        normalize_kernel<<<36, 256>>>(part, protos, cp);
    }
    assign_kernel<<<NB*(NT/16), 128>>>(tembn, ct, protos, cp, tgt, 0);

    loss_kernel<<<dim3(NB*(NT/16), 2), 128, lsm>>>(s0e, s0c, s1e, s1c, ct, cp, protos, tgt);

    finalize_kernel<<<1, 1>>>((float*)d_out);
}

// round 4
// speedup vs baseline: 5.0635x; 1.0405x over previous
#include <cuda_runtime.h>
#include <math.h>

#define NB 2
#define CC 64
#define NP 144
#define NT 2304
#define IH 96
#define IW 96
#define ID 32
#define VOLSZ (IH*IW*ID)
#define NCHUNK 16
#define NPER   (NT/NCHUNK)   // 144
#define PS 161               // padded stride of transposed proto smem [cc][p]
#define NBLK 288

#define INV2SIG2 ((float)(1.0/(2.0*(128.0/2.355)*(128.0/2.355))))

// ---------------- scratch ----------------
__device__ float g_protos[NB*NP*CC];
__device__ float g_cp[NB*NP*3];
__device__ float g_temb [NB*NT*CC];
__device__ float g_tembn[NB*NT*CC];
__device__ float g_ct[NB*NT*3];
__device__ float g_s0e[NB*NT*CC];
__device__ float g_s0c[NB*NT*3];
__device__ float g_s1e[NB*NT*CC];
__device__ float g_s1c[NB*NT*3];
__device__ float g_w  [NB*NT*NP];
__device__ float g_tgt[NB*NT*NP];
__device__ float g_part[NCHUNK*NB*NP*68];
__device__ float g_acc[4];
__device__ unsigned g_bar_count = 0;
__device__ unsigned g_bar_gen   = 0;

// ---------------- grid barrier (all NBLK blocks co-resident) ----------------
__device__ __forceinline__ void grid_barrier(){
    __syncthreads();
    if(threadIdx.x == 0){
        __threadfence();
        unsigned gen = *((volatile unsigned*)&g_bar_gen);
        if(atomicAdd(&g_bar_count, 1u) == NBLK - 1u){
            atomicExch(&g_bar_count, 0u);
            __threadfence();
            atomicExch(&g_bar_gen, gen + 1u);
        } else {
            while(*((volatile unsigned*)&g_bar_gen) == gen){ __nanosleep(32); }
        }
        __threadfence();
    }
    __syncthreads();
}

// ---------------- helpers ----------------
__device__ __forceinline__ float unnorm_reflect(float c, float size){
    float x = ((c + 1.f)*size - 1.f)*0.5f;
    float xr = fabsf(x + 0.5f);
    float extra = fmodf(xr, size);
    float flips = floorf(xr / size);
    float r = (fmodf(flips, 2.f) == 0.f) ? extra : (size - extra);
    r -= 0.5f;
    return fminf(fmaxf(r, 0.f), size - 1.f);
}
__device__ __forceinline__ float warpMax(float x){
    #pragma unroll
    for(int o=16;o;o>>=1) x = fmaxf(x, __shfl_xor_sync(0xffffffffu, x, o));
    return x;
}
__device__ __forceinline__ float warpSum(float x){
    #pragma unroll
    for(int o=16;o;o>>=1) x += __shfl_xor_sync(0xffffffffu, x, o);
    return x;
}

__device__ __forceinline__ void trilerp_setup2(
    int x, int y, int z, int Dr, int Hr, int Wr,
    float tx, float ty, float tz,
    int xi[2], int yi[2], int zi[2], float wx[2], float wy[2], float wz[2],
    float* ux_o, float* uy_o, float* uz_o)
{
    float gx = ((float)x + 0.5f)*2.f/(float)Wr - 1.f + tx;
    float gy = ((float)y + 0.5f)*2.f/(float)Hr - 1.f + ty;
    float gz = ((float)z + 0.5f)*2.f/(float)Dr - 1.f + tz;
    float ux = unnorm_reflect(gx, (float)IW);
    float uy = unnorm_reflect(gy, (float)IH);
    float uz = unnorm_reflect(gz, (float)ID);
    float x0f = floorf(ux), y0f = floorf(uy), z0f = floorf(uz);
    float fx = ux-x0f, fy = uy-y0f, fz = uz-z0f;
    int x0=(int)x0f, y0=(int)y0f, z0=(int)z0f;
    xi[0]=min(max(x0,0),IW-1);  xi[1]=min(max(x0+1,0),IW-1);
    yi[0]=min(max(y0,0),IH-1);  yi[1]=min(max(y0+1,0),IH-1);
    zi[0]=min(max(z0,0),ID-1);  zi[1]=min(max(z0+1,0),ID-1);
    wx[0]=1.f-fx; wx[1]=fx; wy[0]=1.f-fy; wy[1]=fy; wz[0]=1.f-fz; wz[1]=fz;
    *ux_o=ux; *uy_o=uy; *uz_o=uz;
}

__device__ __forceinline__ float gather8(const float* __restrict__ base,
    const int xi[2], const int yi[2], const int zi[2],
    const float wx[2], const float wy[2], const float wz[2])
{
    float val = 0.f;
    #pragma unroll
    for(int dz=0; dz<2; dz++)
      #pragma unroll
      for(int dy=0; dy<2; dy++)
        #pragma unroll
        for(int dx=0; dx<2; dx++)
            val += wx[dx]*wy[dy]*wz[dz] *
                   base[((size_t)yi[dy]*IW + xi[dx])*ID + zi[dz]];
    return val;
}

// ---------------- merged sampling: grid (1152, 4), 256 thr ----------------
struct SampleArgs {
    const float* emb[3]; const float* jit[3];
    float* outn[3]; float* outraw[3]; float* outc[3];
    const float* pemb; const float* pjit;
    float* pout; float* pcoord;
};

__global__ void sample_all_kernel(SampleArgs a)
{
    int s = blockIdx.y;
    int pt = threadIdx.x >> 6;
    int c  = threadIdx.x & 63;
    const float *emb, *jit;
    float *outn, *outraw, *outc;
    int gp, v, n, Dr, Hr, Wr; float sd, sh, sw_;
    if(s < 3){
        gp = blockIdx.x*4 + pt; v = gp/NT; n = gp - v*NT;
        Dr=16; Hr=12; Wr=12; sd=2.f/32.f; sh=8.f/96.f; sw_=8.f/96.f;
        emb=a.emb[s]; jit=a.jit[s]; outn=a.outn[s]; outraw=a.outraw[s]; outc=a.outc[s];
    } else {
        if(blockIdx.x >= 72) return;
        gp = blockIdx.x*4 + pt; v = gp/NP; n = gp - v*NP;
        Dr=4; Hr=6; Wr=6; sd=8.f/32.f; sh=16.f/96.f; sw_=16.f/96.f;
        emb=a.pemb; jit=a.pjit; outn=a.pout; outraw=nullptr; outc=a.pcoord;
    }
    int HW = Hr*Wr;
    int z = n/HW; int rem = n - z*HW; int yy = rem/Wr; int xx = rem - yy*Wr;
    float tz = (jit[v*3+0]-0.5f)*2.f*sd;
    float ty = (jit[v*3+1]-0.5f)*2.f*sh;
    float tx = (jit[v*3+2]-0.5f)*2.f*sw_;

    int xi[2], yi[2], zi[2]; float wx[2], wy[2], wz[2], ux, uy, uz;
    trilerp_setup2(xx,yy,z,Dr,Hr,Wr,tx,ty,tz,xi,yi,zi,wx,wy,wz,&ux,&uy,&uz);

    float val = gather8(emb + (size_t)(v*CC + c)*VOLSZ, xi,yi,zi,wx,wy,wz);

    __shared__ float ssq[256];
    int t = threadIdx.x, gb = pt*64;
    ssq[t] = val*val;
    __syncthreads();
    if(c<32) ssq[t]+=ssq[t+32]; __syncthreads();
    if(c<16) ssq[t]+=ssq[t+16]; __syncthreads();
    if(c< 8) ssq[t]+=ssq[t+ 8]; __syncthreads();
    if(c< 4) ssq[t]+=ssq[t+ 4]; __syncthreads();
    if(c< 2) ssq[t]+=ssq[t+ 2]; __syncthreads();
    if(c< 1) ssq[t]+=ssq[t+ 1]; __syncthreads();
    float inv = 1.f / fmaxf(sqrtf(ssq[gb]), 1e-8f);

    size_t o = (size_t)gp*CC + c;
    outn[o] = val*inv;
    if(outraw) outraw[o] = val;
    if(c==0){
        outc[(size_t)gp*3 + 0] = uy;
        outc[(size_t)gp*3 + 1] = ux;
        outc[(size_t)gp*3 + 2] = uz;
    }
}

// ================= fused EM + loss persistent kernel =================
// 288 blocks x 128 threads; dyn smem = 70784 bytes.

__device__ __forceinline__ void assign_phase(
    float* dyn, const float* __restrict__ tn, const float* __restrict__ ct,
    const float* __restrict__ pr, const float* __restrict__ cp,
    float* __restrict__ out, int useGauss)
{
    float* spT  = dyn;            // 64*PS
    float* scpx = spT + 64*PS;    // 160
    float* scpy = scpx + 160;
    float* scpz = scpy + 160;

    int tid = threadIdx.x, lane = tid&31, wid = tid>>5;
    int v  = blockIdx.x / (NT/16);
    int n0 = (blockIdx.x - v*(NT/16))*16;

    for(int i=tid; i<NP*CC; i+=128){
        int p = i>>6, cc2 = i&63;
        spT[cc2*PS + p] = pr[(size_t)v*NP*CC + i];
    }
    for(int i=tid; i<64*(PS-NP); i+=128){
        int cc2 = i/(PS-NP), p = NP + i%(PS-NP);
        spT[cc2*PS + p] = 0.f;
    }
    for(int i=tid; i<160; i+=128){
        float x=0.f, yv=0.f, z=0.f;
        if(i<NP){ x=cp[(v*NP+i)*3+0]; yv=cp[(v*NP+i)*3+1]; z=cp[(v*NP+i)*3+2]; }
        scpx[i]=x; scpy[i]=yv; scpz[i]=z;
    }
    __syncthreads();

    size_t gnb = (size_t)v*NT + n0 + wid*4;
    float r[2][4], px[4], py[4], pz[4];
    #pragma unroll
    for(int q=0;q<4;q++){
        r[0][q] = tn[(gnb+q)*64 + lane];
        r[1][q] = tn[(gnb+q)*64 + 32 + lane];
        px[q] = ct[(gnb+q)*3+0]; py[q] = ct[(gnb+q)*3+1]; pz[q] = ct[(gnb+q)*3+2];
    }

    float acc[4][5];
    #pragma unroll
    for(int q=0;q<4;q++){
        #pragma unroll
        for(int j=0;j<5;j++) acc[q][j]=0.f;
    }
    #pragma unroll
    for(int h=0;h<2;h++){
        #pragma unroll 8
        for(int cc2=0; cc2<32; cc2++){
            const float* row = spT + (h*32+cc2)*PS + lane;
            float p0=row[0], p1=row[32], p2=row[64], p3=row[96], p4=row[128];
            #pragma unroll
            for(int q=0;q<4;q++){
                float vv = __shfl_sync(0xffffffffu, r[h][q], cc2);
                acc[q][0]=fmaf(vv,p0,acc[q][0]);
                acc[q][1]=fmaf(vv,p1,acc[q][1]);
                acc[q][2]=fmaf(vv,p2,acc[q][2]);
                acc[q][3]=fmaf(vv,p3,acc[q][3]);
                acc[q][4]=fmaf(vv,p4,acc[q][4]);
            }
        }
    }

    bool v4 = lane < 16;
    #pragma unroll
    for(int q=0;q<4;q++){
        float lg[5], mx = -1e30f;
        #pragma unroll
        for(int j=0;j<5;j++){
            lg[j] = acc[q][j]*(1.f/0.015f);
            if(j<4 || v4) mx = fmaxf(mx, lg[j]);
        }
        mx = warpMax(mx);
        float e[5], sum = 0.f;
        #pragma unroll
        for(int j=0;j<5;j++){ e[j] = (j<4||v4) ? expf(lg[j]-mx) : 0.f; sum += e[j]; }
        sum = warpSum(sum);
        float invs = 1.f/sum;
        #pragma unroll
        for(int j=0;j<5;j++){
            if(j==4 && !v4) continue;
            int p = lane + 32*j;
            float aa = e[j]*invs;
            if(useGauss){
                float dx = px[q]-scpx[p];
                float dy = py[q]-scpy[p];
                float dz = (pz[q]-scpz[p])*2.f;
                aa *= expf(-(dx*dx+dy*dy+dz*dz)*INV2SIG2);
            }
            out[(gnb+q)*NP + p] = aa;
        }
    }
}

__device__ __forceinline__ void update_phase(
    float* dyn, const float* __restrict__ w, const float* __restrict__ temb,
    const float* __restrict__ ct, float* __restrict__ part)
{
    float* sw_ = dyn;             // NPER*16
    float* st  = sw_ + NPER*16;   // NPER*64
    float* sc  = st + NPER*64;    // NPER*3

    int tid = threadIdx.x, lane = tid&31, wp = tid>>5;
    int bx = blockIdx.x;
    int v  = bx / (9*NCHUNK);
    int rr = bx - v*(9*NCHUNK);
    int ch = rr / 9, pblk = rr - ch*9;
    int p0b = pblk*16;
    size_t gn0 = (size_t)v*NT + ch*NPER;

    for(int i=tid; i<NPER*16; i+=128){
        int n = i>>4, pj = i&15;
        sw_[i] = w[(gn0+n)*NP + p0b + pj];
    }
    {
        const float4* src = (const float4*)(temb + gn0*64);
        float4* dst = (float4*)st;
        for(int i=tid; i<NPER*16; i+=128) dst[i] = src[i];
    }
    for(int i=tid; i<NPER*3; i+=128) sc[i] = ct[gn0*3 + i];
    __syncthreads();

    int pw = p0b + wp*4;
    float a0[4], a1[4], dn[4], ca[4];
    #pragma unroll
    for(int j=0;j<4;j++){ a0[j]=0.f; a1[j]=0.f; dn[j]=0.f; ca[j]=0.f; }
    #pragma unroll 2
    for(int n=0;n<NPER;n++){
        float t0 = st[n*64+lane], t1 = st[n*64+32+lane];
        float cv = (lane<3) ? sc[n*3+lane] : 0.f;
        #pragma unroll
        for(int j=0;j<4;j++){
            float wv = sw_[n*16 + wp*4 + j];
            a0[j] = fmaf(wv,t0,a0[j]);
            a1[j] = fmaf(wv,t1,a1[j]);
            dn[j] += wv;
            ca[j] = fmaf(wv,cv,ca[j]);
        }
    }
    #pragma unroll
    for(int j=0;j<4;j++){
        int p = pw + j;
        size_t b0 = ((size_t)(ch*NB + v)*NP + p)*68;
        part[b0+lane]    = a0[j];
        part[b0+32+lane] = a1[j];
        if(lane==0) part[b0+64] = dn[j];
        if(lane<3)  part[b0+65+lane] = ca[j];
    }
}

__device__ __forceinline__ void normalize_phase(
    float* dyn, const float* __restrict__ part,
    float* __restrict__ pr, float* __restrict__ cp)
{
    float* comb = dyn;   // 4*68
    int lane = threadIdx.x & 31, wid = threadIdx.x >> 5;
    int b = blockIdx.x;
    int v = b / NP, p = b - v*NP;

    float a0=0.f, a1=0.f, den=0.f, ca=0.f;
    #pragma unroll
    for(int k=0;k<4;k++){
        int ch = wid + 4*k;
        size_t bb = ((size_t)(ch*NB + v)*NP + p)*68;
        a0  += part[bb+lane];
        a1  += part[bb+32+lane];
        den += part[bb+64];
        if(lane<3) ca += part[bb+65+lane];
    }
    comb[wid*68+lane]    = a0;
    comb[wid*68+32+lane] = a1;
    if(lane==0) comb[wid*68+64] = den;
    if(lane<3)  comb[wid*68+65+lane] = ca;
    __syncthreads();
    if(wid==0){
        float s0 = comb[lane]      + comb[68+lane]      + comb[136+lane]      + comb[204+lane];
        float s1 = comb[32+lane]   + comb[68+32+lane]   + comb[136+32+lane]   + comb[204+32+lane];
        float dd = comb[64]        + comb[68+64]        + comb[136+64]        + comb[204+64];
        float cc2 = 0.f;
        if(lane<3) cc2 = comb[65+lane] + comb[68+65+lane] + comb[136+65+lane] + comb[204+65+lane];
        float d = dd + 1e-8f;
        float q0 = s0/d, q1 = s1/d;
        float ss = warpSum(q0*q0 + q1*q1);
        float inv = 1.f / fmaxf(sqrtf(ss), 1e-8f);
        pr[(size_t)(v*NP+p)*64 + lane]      = q0*inv;
        pr[(size_t)(v*NP+p)*64 + 32 + lane] = q1*inv;
        if(lane<3) cp[(v*NP+p)*3 + lane] = cc2/d;
    }
    __syncthreads();
}

__device__ __forceinline__ void loss_phase(
    float* dyn,
    const float* __restrict__ se0, const float* __restrict__ sc0,
    const float* __restrict__ se1, const float* __restrict__ sc1,
    const float* __restrict__ ct,  const float* __restrict__ cp,
    const float* __restrict__ pr,  const float* __restrict__ tg)
{
    float* spT  = dyn;               // 64*PS
    float* sctx = spT + 64*PS;       // NT
    float* scty = sctx + NT;
    float* sctz = scty + NT;
    float* scpx = sctz + NT;         // 160
    float* scpy = scpx + 160;
    float* scpz = scpy + 160;
    __shared__ float bacc[2];

    int tid = threadIdx.x, lane = tid&31, wid = tid>>5;
    int v  = blockIdx.x / (NT/16);
    int m0 = (blockIdx.x - v*(NT/16))*16;

    for(int i=tid; i<NP*CC; i+=128){
        int p = i>>6, cc2 = i&63;
        spT[cc2*PS + p] = pr[(size_t)v*NP*CC + i];
    }
    for(int i=tid; i<64*(PS-NP); i+=128){
        int cc2 = i/(PS-NP), p = NP + i%(PS-NP);
        spT[cc2*PS + p] = 0.f;
    }
    for(int i=tid; i<NT; i+=128){
        sctx[i] = ct[((size_t)v*NT + i)*3 + 0];
        scty[i] = ct[((size_t)v*NT + i)*3 + 1];
        sctz[i] = ct[((size_t)v*NT + i)*3 + 2];
    }
    for(int i=tid; i<160; i+=128){
        float x=0.f, yv=0.f, z=0.f;
        if(i<NP){ x=cp[(v*NP+i)*3+0]; yv=cp[(v*NP+i)*3+1]; z=cp[(v*NP+i)*3+2]; }
        scpx[i]=x; scpy[i]=yv; scpz[i]=z;
    }

    for(int sidx=0; sidx<2; sidx++){
        const float* se  = sidx ? se1 : se0;
        const float* scc = sidx ? sc1 : sc0;
        if(tid < 2) bacc[tid] = 0.f;
        __syncthreads();

        size_t gmb = (size_t)v*NT + m0 + wid*4;
        float r[2][4], sx[4], sy[4], sz[4];
        #pragma unroll
        for(int q=0;q<4;q++){
            r[0][q] = se[(gmb+q)*64 + lane];
            r[1][q] = se[(gmb+q)*64 + 32 + lane];
            sx[q] = scc[(gmb+q)*3+0]; sy[q] = scc[(gmb+q)*3+1]; sz[q] = scc[(gmb+q)*3+2];
        }

        float best[4] = {1e30f,1e30f,1e30f,1e30f};
        int   bi[4]   = {NT,NT,NT,NT};
        for(int nn=lane; nn<NT; nn+=32){
            float tx = sctx[nn], ty = scty[nn], tz = sctz[nn];
            #pragma unroll
            for(int q=0;q<4;q++){
                float dx = sx[q]-tx, dy = sy[q]-ty, dz = (sz[q]-tz)*2.f;
                float d2 = fmaf(dx,dx, fmaf(dy,dy, dz*dz));
                if(d2 < best[q]){ best[q] = d2; bi[q] = nn; }
            }
        }
        #pragma unroll
        for(int q=0;q<4;q++){
            #pragma unroll
            for(int o=16;o;o>>=1){
                float ov = __shfl_xor_sync(0xffffffffu, best[q], o);
                int   oi = __shfl_xor_sync(0xffffffffu, bi[q], o);
                if(ov < best[q] || (ov == best[q] && oi < bi[q])){ best[q]=ov; bi[q]=oi; }
            }
        }

        float acc[4][5];
        #pragma unroll
        for(int q=0;q<4;q++){
            #pragma unroll
            for(int j=0;j<5;j++) acc[q][j]=0.f;
        }
        #pragma unroll
        for(int h=0;h<2;h++){
            #pragma unroll 8
            for(int cc2=0; cc2<32; cc2++){
                const float* row = spT + (h*32+cc2)*PS + lane;
                float p0=row[0], p1=row[32], p2=row[64], p3=row[96], p4=row[128];
                #pragma unroll
                for(int q=0;q<4;q++){
                    float vv = __shfl_sync(0xffffffffu, r[h][q], cc2);
                    acc[q][0]=fmaf(vv,p0,acc[q][0]);
                    acc[q][1]=fmaf(vv,p1,acc[q][1]);
                    acc[q][2]=fmaf(vv,p2,acc[q][2]);
                    acc[q][3]=fmaf(vv,p3,acc[q][3]);
                    acc[q][4]=fmaf(vv,p4,acc[q][4]);
                }
            }
        }

        bool v4 = lane < 16;
        #pragma unroll
        for(int q=0;q<4;q++){
            float lg[5], mx = -1e30f;
            #pragma unroll
            for(int j=0;j<5;j++){
                lg[j] = acc[q][j]*(1.f/0.03f);
                if(j<4 || v4) mx = fmaxf(mx, lg[j]);
            }
            mx = warpMax(mx);
            float sum = 0.f;
            #pragma unroll
            for(int j=0;j<5;j++) sum += (j<4||v4) ? expf(lg[j]-mx) : 0.f;
            sum = warpSum(sum);
            float lse = mx + logf(sum);

            const float* tgrow = tg + ((size_t)v*NT + bi[q])*NP;
            float ts = 0.f, ctr = 0.f;
            #pragma unroll
            for(int j=0;j<5;j++){
                if(j==4 && !v4) continue;
                int p = lane + 32*j;
                float dx = sx[q]-scpx[p];
                float dy = sy[q]-scpy[p];
                float dz = (sz[q]-scpz[p])*2.f;
                float pos = (expf(-(dx*dx+dy*dy+dz*dz)*INV2SIG2) >= 0.5f) ? 1.f : 0.f;
                float t = tgrow[p]*pos;
                ts  += t;
                ctr += t*(lg[j]-lse);
            }
            ts  = warpSum(ts);
            ctr = warpSum(ctr);
            if(lane==0 && sqrtf(best[q]) <= 3.0f){
                atomicAdd(&bacc[0], -ctr/(ts + 1e-8f));
                atomicAdd(&bacc[1], 1.f);
            }
        }
        __syncthreads();
        if(tid==0){
            atomicAdd(&g_acc[sidx*2+0], bacc[0]);
            atomicAdd(&g_acc[sidx*2+1], bacc[1]);
        }
        __syncthreads();
    }
}

__global__ void __launch_bounds__(128)
fused_em_kernel(float* __restrict__ out)
{
    extern __shared__ float dyn[];
    float* protos = g_protos;
    float* cp     = g_cp;

    if(blockIdx.x == 0 && threadIdx.x < 4) g_acc[threadIdx.x] = 0.f;

    for(int it=0; it<3; it++){
        assign_phase(dyn, g_tembn, g_ct, protos, cp, g_w, 1);
        grid_barrier();
        update_phase(dyn, g_w, g_temb, g_ct, g_part);
        grid_barrier();
        normalize_phase(dyn, g_part, protos, cp);
        grid_barrier();
    }
    assign_phase(dyn, g_tembn, g_ct, protos, cp, g_tgt, 0);
    grid_barrier();
    loss_phase(dyn, g_s0e, g_s0c, g_s1e, g_s1c, g_ct, cp, protos, g_tgt);
    grid_barrier();

    if(blockIdx.x == 0 && threadIdx.x == 0){
        out[0] = 0.5f*( g_acc[0]/(g_acc[1] + 1e-8f) + g_acc[2]/(g_acc[3] + 1e-8f) );
    }
}

// ---------------- host launch ----------------
extern "C" void kernel_launch(void* const* d_in, const int* in_sizes, int n_in,
                              void* d_out, int out_size)
{
    const float* e0  = (const float*)d_in[0];
    const float* e1  = (const float*)d_in[1];
    const float* et  = (const float*)d_in[2];
    const float* jp  = (const float*)d_in[7];
    const float* j0  = (const float*)d_in[8];
    const float* j1  = (const float*)d_in[9];
    const float* jt  = (const float*)d_in[10];

    float *protos,*cp,*temb,*tembn,*ct,*s0e,*s0c,*s1e,*s1c;
    cudaGetSymbolAddress((void**)&protos, g_protos);
    cudaGetSymbolAddress((void**)&cp,     g_cp);
    cudaGetSymbolAddress((void**)&temb,   g_temb);
    cudaGetSymbolAddress((void**)&tembn,  g_tembn);
    cudaGetSymbolAddress((void**)&ct,     g_ct);
    cudaGetSymbolAddress((void**)&s0e,    g_s0e);
    cudaGetSymbolAddress((void**)&s0c,    g_s0c);
    cudaGetSymbolAddress((void**)&s1e,    g_s1e);
    cudaGetSymbolAddress((void**)&s1c,    g_s1c);

    size_t fsm = (size_t)(64*PS + 3*NT + 3*160)*sizeof(float);   // 70784 B
    cudaFuncSetAttribute(fused_em_kernel, cudaFuncAttributeMaxDynamicSharedMemorySize, (int)fsm);

    SampleArgs a;
    a.emb[0]=et;  a.emb[1]=e0;  a.emb[2]=e1;
    a.jit[0]=jt;  a.jit[1]=j0;  a.jit[2]=j1;
    a.outn[0]=tembn; a.outn[1]=s0e; a.outn[2]=s1e;
    a.outraw[0]=temb; a.outraw[1]=nullptr; a.outraw[2]=nullptr;
    a.outc[0]=ct; a.outc[1]=s0c; a.outc[2]=s1c;
    a.pemb=et; a.pjit=jp; a.pout=protos; a.pcoord=cp;
    sample_all_kernel<<<dim3(NB*NT/4, 4), 256>>>(a);

    fused_em_kernel<<<NBLK, 128, fsm>>>((float*)d_out);
}

// round 6
// speedup vs baseline: 6.0895x; 1.2026x over previous
#include <cuda_runtime.h>
#include <math.h>

#define NB 2
#define CC 64
#define NP 144
#define NT 2304
#define IH 96
#define IW 96
#define ID 32
#define VOLSZ (IH*IW*ID)
#define NCHUNK 16
#define NPER   (NT/NCHUNK)   // 144
#define PS 161               // padded stride of transposed proto smem [cc][p]
#define NBLK 288
#define TPB 256

#define INV2SIG2 ((float)(1.0/(2.0*(128.0/2.355)*(128.0/2.355))))

// ---------------- scratch ----------------
__device__ float g_protos[NB*NP*CC];
__device__ float g_cp[NB*NP*3];
__device__ float g_temb [NB*NT*CC];
__device__ float g_tembn[NB*NT*CC];
__device__ float g_ct[NB*NT*3];
__device__ float g_s0e[NB*NT*CC];
__device__ float g_s0c[NB*NT*3];
__device__ float g_s1e[NB*NT*CC];
__device__ float g_s1c[NB*NT*3];
__device__ float g_w  [NB*NT*NP];
__device__ float g_tgt[NB*NT*NP];
__device__ float g_part[NCHUNK*NB*NP*68];
__device__ float g_acc[4];
__device__ unsigned g_bar_count = 0;
__device__ unsigned g_bar_gen   = 0;

// ---------------- grid barrier ----------------
__device__ __forceinline__ void grid_barrier(){
    __syncthreads();
    if(threadIdx.x == 0){
        __threadfence();
        unsigned gen = *((volatile unsigned*)&g_bar_gen);
        if(atomicAdd(&g_bar_count, 1u) == NBLK - 1u){
            atomicExch(&g_bar_count, 0u);
            __threadfence();
            atomicExch(&g_bar_gen, gen + 1u);
        } else {
            while(*((volatile unsigned*)&g_bar_gen) == gen){ __nanosleep(32); }
        }
        __threadfence();
    }
    __syncthreads();
}

// ---------------- helpers ----------------
__device__ __forceinline__ float unnorm_reflect(float c, float size){
    float x = ((c + 1.f)*size - 1.f)*0.5f;
    float xr = fabsf(x + 0.5f);
    float extra = fmodf(xr, size);
    float flips = floorf(xr / size);
    float r = (fmodf(flips, 2.f) == 0.f) ? extra : (size - extra);
    r -= 0.5f;
    return fminf(fmaxf(r, 0.f), size - 1.f);
}
__device__ __forceinline__ float warpMax(float x){
    #pragma unroll
    for(int o=16;o;o>>=1) x = fmaxf(x, __shfl_xor_sync(0xffffffffu, x, o));
    return x;
}
__device__ __forceinline__ float warpSum(float x){
    #pragma unroll
    for(int o=16;o;o>>=1) x += __shfl_xor_sync(0xffffffffu, x, o);
    return x;
}

__device__ __forceinline__ void trilerp_setup2(
    int x, int y, int z, int Dr, int Hr, int Wr,
    float tx, float ty, float tz,
    int xi[2], int yi[2], int zi[2], float wx[2], float wy[2], float wz[2],
    float* ux_o, float* uy_o, float* uz_o)
{
    float gx = ((float)x + 0.5f)*2.f/(float)Wr - 1.f + tx;
    float gy = ((float)y + 0.5f)*2.f/(float)Hr - 1.f + ty;
    float gz = ((float)z + 0.5f)*2.f/(float)Dr - 1.f + tz;
    float ux = unnorm_reflect(gx, (float)IW);
    float uy = unnorm_reflect(gy, (float)IH);
    float uz = unnorm_reflect(gz, (float)ID);
    float x0f = floorf(ux), y0f = floorf(uy), z0f = floorf(uz);
    float fx = ux-x0f, fy = uy-y0f, fz = uz-z0f;
    int x0=(int)x0f, y0=(int)y0f, z0=(int)z0f;
    xi[0]=min(max(x0,0),IW-1);  xi[1]=min(max(x0+1,0),IW-1);
    yi[0]=min(max(y0,0),IH-1);  yi[1]=min(max(y0+1,0),IH-1);
    zi[0]=min(max(z0,0),ID-1);  zi[1]=min(max(z0+1,0),ID-1);
    wx[0]=1.f-fx; wx[1]=fx; wy[0]=1.f-fy; wy[1]=fy; wz[0]=1.f-fz; wz[1]=fz;
    *ux_o=ux; *uy_o=uy; *uz_o=uz;
}

__device__ __forceinline__ float gather8(const float* __restrict__ base,
    const int xi[2], const int yi[2], const int zi[2],
    const float wx[2], const float wy[2], const float wz[2])
{
    float val = 0.f;
    #pragma unroll
    for(int dz=0; dz<2; dz++)
      #pragma unroll
      for(int dy=0; dy<2; dy++)
        #pragma unroll
        for(int dx=0; dx<2; dx++)
            val += wx[dx]*wy[dy]*wz[dz] *
                   base[((size_t)yi[dy]*IW + xi[dx])*ID + zi[dz]];
    return val;
}

// ---------------- merged sampling: grid (1152, 4), 256 thr ----------------
struct SampleArgs {
    const float* emb[3]; const float* jit[3];
    float* outn[3]; float* outraw[3]; float* outc[3];
    const float* pemb; const float* pjit;
    float* pout; float* pcoord;
};

__global__ void sample_all_kernel(SampleArgs a)
{
    int s = blockIdx.y;
    int pt = threadIdx.x >> 6;
    int c  = threadIdx.x & 63;
    const float *emb, *jit;
    float *outn, *outraw, *outc;
    int gp, v, n, Dr, Hr, Wr; float sd, sh, sw_;
    if(s < 3){
        gp = blockIdx.x*4 + pt; v = gp/NT; n = gp - v*NT;
        Dr=16; Hr=12; Wr=12; sd=2.f/32.f; sh=8.f/96.f; sw_=8.f/96.f;
        emb=a.emb[s]; jit=a.jit[s]; outn=a.outn[s]; outraw=a.outraw[s]; outc=a.outc[s];
    } else {
        if(blockIdx.x >= 72) return;
        gp = blockIdx.x*4 + pt; v = gp/NP; n = gp - v*NP;
        Dr=4; Hr=6; Wr=6; sd=8.f/32.f; sh=16.f/96.f; sw_=16.f/96.f;
        emb=a.pemb; jit=a.pjit; outn=a.pout; outraw=nullptr; outc=a.pcoord;
    }
    int HW = Hr*Wr;
    int z = n/HW; int rem = n - z*HW; int yy = rem/Wr; int xx = rem - yy*Wr;
    float tz = (jit[v*3+0]-0.5f)*2.f*sd;
    float ty = (jit[v*3+1]-0.5f)*2.f*sh;
    float tx = (jit[v*3+2]-0.5f)*2.f*sw_;

    int xi[2], yi[2], zi[2]; float wx[2], wy[2], wz[2], ux, uy, uz;
    trilerp_setup2(xx,yy,z,Dr,Hr,Wr,tx,ty,tz,xi,yi,zi,wx,wy,wz,&ux,&uy,&uz);

    float val = gather8(emb + (size_t)(v*CC + c)*VOLSZ, xi,yi,zi,wx,wy,wz);

    __shared__ float ssq[256];
    int t = threadIdx.x, gb = pt*64;
    ssq[t] = val*val;
    __syncthreads();
    if(c<32) ssq[t]+=ssq[t+32]; __syncthreads();
    if(c<16) ssq[t]+=ssq[t+16]; __syncthreads();
    if(c< 8) ssq[t]+=ssq[t+ 8]; __syncthreads();
    if(c< 4) ssq[t]+=ssq[t+ 4]; __syncthreads();
    if(c< 2) ssq[t]+=ssq[t+ 2]; __syncthreads();
    if(c< 1) ssq[t]+=ssq[t+ 1]; __syncthreads();
    float inv = 1.f / fmaxf(sqrtf(ssq[gb]), 1e-8f);

    size_t o = (size_t)gp*CC + c;
    outn[o] = val*inv;
    if(outraw) outraw[o] = val;
    if(c==0){
        outc[(size_t)gp*3 + 0] = uy;   // channel 0 = h
        outc[(size_t)gp*3 + 1] = ux;   // channel 1 = w
        outc[(size_t)gp*3 + 2] = uz;   // channel 2 = d
    }
}

// ================= fused EM + loss persistent kernel =================
// 288 blocks x 256 threads; dyn smem = 47808 bytes.

__device__ __forceinline__ void stage_protos(float* spT, const float* __restrict__ pr, int v){
    int tid = threadIdx.x;
    const float4* src = (const float4*)(pr + (size_t)v*NP*CC);
    for(int i4 = tid; i4 < NP*CC/4; i4 += TPB){
        float4 q = src[i4];
        int i = i4*4;
        int p = i>>6, c0 = i&63;
        spT[(c0+0)*PS + p] = q.x;
        spT[(c0+1)*PS + p] = q.y;
        spT[(c0+2)*PS + p] = q.z;
        spT[(c0+3)*PS + p] = q.w;
    }
    for(int i=tid; i<64*(PS-NP); i+=TPB){
        int cc2 = i/(PS-NP), p = NP + i%(PS-NP);
        spT[cc2*PS + p] = 0.f;
    }
}

__device__ __forceinline__ void dot2(const float* __restrict__ spT, int lane,
                                     const float r[2][2], float acc[2][5]){
    #pragma unroll
    for(int q=0;q<2;q++)
        #pragma unroll
        for(int j=0;j<5;j++) acc[q][j]=0.f;
    #pragma unroll
    for(int h=0;h<2;h++){
        #pragma unroll 8
        for(int cc2=0; cc2<32; cc2++){
            const float* row = spT + (h*32+cc2)*PS + lane;
            float p0=row[0], p1=row[32], p2=row[64], p3=row[96], p4=row[128];
            #pragma unroll
            for(int q=0;q<2;q++){
                float vv = __shfl_sync(0xffffffffu, r[h][q], cc2);
                acc[q][0]=fmaf(vv,p0,acc[q][0]);
                acc[q][1]=fmaf(vv,p1,acc[q][1]);
                acc[q][2]=fmaf(vv,p2,acc[q][2]);
                acc[q][3]=fmaf(vv,p3,acc[q][3]);
                acc[q][4]=fmaf(vv,p4,acc[q][4]);
            }
        }
    }
}

__device__ __forceinline__ void assign_phase(
    float* dyn, const float* __restrict__ tn, const float* __restrict__ ct,
    const float* __restrict__ pr, const float* __restrict__ cp,
    float* __restrict__ out, int useGauss)
{
    float* spT  = dyn;            // 64*PS
    float* scpx = spT + 64*PS;    // 160
    float* scpy = scpx + 160;
    float* scpz = scpy + 160;

    int tid = threadIdx.x, lane = tid&31, wid = tid>>5;
    int v  = blockIdx.x / (NT/16);
    int n0 = (blockIdx.x - v*(NT/16))*16;

    stage_protos(spT, pr, v);
    for(int i=tid; i<160; i+=TPB){
        float x=0.f, yv=0.f, z=0.f;
        if(i<NP){ x=cp[(v*NP+i)*3+0]; yv=cp[(v*NP+i)*3+1]; z=cp[(v*NP+i)*3+2]; }
        scpx[i]=x; scpy[i]=yv; scpz[i]=z;
    }
    __syncthreads();

    size_t gnb = (size_t)v*NT + n0 + wid*2;
    float r[2][2], px[2], py[2], pz[2];
    #pragma unroll
    for(int q=0;q<2;q++){
        r[0][q] = tn[(gnb+q)*64 + lane];
        r[1][q] = tn[(gnb+q)*64 + 32 + lane];
        px[q] = ct[(gnb+q)*3+0]; py[q] = ct[(gnb+q)*3+1]; pz[q] = ct[(gnb+q)*3+2];
    }

    float acc[2][5];
    dot2(spT, lane, r, acc);

    bool v4 = lane < 16;
    #pragma unroll
    for(int q=0;q<2;q++){
        float lg[5], mx = -1e30f;
        #pragma unroll
        for(int j=0;j<5;j++){
            lg[j] = acc[q][j]*(1.f/0.015f);
            if(j<4 || v4) mx = fmaxf(mx, lg[j]);
        }
        mx = warpMax(mx);
        float e[5], sum = 0.f;
        #pragma unroll
        for(int j=0;j<5;j++){ e[j] = (j<4||v4) ? expf(lg[j]-mx) : 0.f; sum += e[j]; }
        sum = warpSum(sum);
        float invs = 1.f/sum;
        #pragma unroll
        for(int j=0;j<5;j++){
            if(j==4 && !v4) continue;
            int p = lane + 32*j;
            float aa = e[j]*invs;
            if(useGauss){
                float dx = px[q]-scpx[p];
                float dy = py[q]-scpy[p];
                float dz = (pz[q]-scpz[p])*2.f;
                aa *= expf(-(dx*dx+dy*dy+dz*dz)*INV2SIG2);
            }
            out[(gnb+q)*NP + p] = aa;
        }
    }
}

__device__ __forceinline__ void update_phase(
    float* dyn, const float* __restrict__ w, const float* __restrict__ temb,
    const float* __restrict__ ct, float* __restrict__ part)
{
    float* sw_ = dyn;             // NPER*16
    float* st  = sw_ + NPER*16;   // NPER*64
    float* sc  = st + NPER*64;    // NPER*3

    int tid = threadIdx.x, lane = tid&31, wp = tid>>5;
    int bx = blockIdx.x;
    int v  = bx / (9*NCHUNK);
    int rr = bx - v*(9*NCHUNK);
    int ch = rr / 9, pblk = rr - ch*9;
    int p0b = pblk*16;
    size_t gn0 = (size_t)v*NT + ch*NPER;

    for(int i=tid; i<NPER*16; i+=TPB){
        int n = i>>4, pj = i&15;
        sw_[i] = w[(gn0+n)*NP + p0b + pj];
    }
    {
        const float4* src = (const float4*)(temb + gn0*64);
        float4* dst = (float4*)st;
        for(int i=tid; i<NPER*16; i+=TPB) dst[i] = src[i];
    }
    for(int i=tid; i<NPER*3; i+=TPB) sc[i] = ct[gn0*3 + i];
    __syncthreads();

    float a0[2]={0.f,0.f}, a1[2]={0.f,0.f}, dn[2]={0.f,0.f}, ca[2]={0.f,0.f};
    #pragma unroll 4
    for(int n=0;n<NPER;n++){
        float2 wv = *(const float2*)&sw_[n*16 + wp*2];
        float t0 = st[n*64+lane], t1 = st[n*64+32+lane];
        float cv = (lane<3) ? sc[n*3+lane] : 0.f;
        a0[0] = fmaf(wv.x,t0,a0[0]); a1[0] = fmaf(wv.x,t1,a1[0]);
        a0[1] = fmaf(wv.y,t0,a0[1]); a1[1] = fmaf(wv.y,t1,a1[1]);
        dn[0] += wv.x; dn[1] += wv.y;
        ca[0] = fmaf(wv.x,cv,ca[0]); ca[1] = fmaf(wv.y,cv,ca[1]);
    }
    #pragma unroll
    for(int j=0;j<2;j++){
        int p = p0b + wp*2 + j;
        size_t b0 = ((size_t)(ch*NB + v)*NP + p)*68;
        part[b0+lane]    = a0[j];
        part[b0+32+lane] = a1[j];
        if(lane==0) part[b0+64] = dn[j];
        if(lane<3)  part[b0+65+lane] = ca[j];
    }
}

__device__ __forceinline__ void normalize_phase(
    float* dyn, const float* __restrict__ part,
    float* __restrict__ pr, float* __restrict__ cp)
{
    float* comb = dyn;   // 8*68
    int lane = threadIdx.x & 31, wid = threadIdx.x >> 5;
    int b = blockIdx.x;
    int v = b / NP, p = b - v*NP;

    float a0=0.f, a1=0.f, den=0.f, ca=0.f;
    #pragma unroll
    for(int k=0;k<2;k++){
        int ch = wid + 8*k;
        size_t bb = ((size_t)(ch*NB + v)*NP + p)*68;
        a0  += part[bb+lane];
        a1  += part[bb+32+lane];
        den += part[bb+64];
        if(lane<3) ca += part[bb+65+lane];
    }
    comb[wid*68+lane]    = a0;
    comb[wid*68+32+lane] = a1;
    if(lane==0) comb[wid*68+64] = den;
    if(lane<3)  comb[wid*68+65+lane] = ca;
    __syncthreads();
    if(wid==0){
        float s0=0.f, s1=0.f, dd=0.f, cc2=0.f;
        #pragma unroll
        for(int k=0;k<8;k++){
            s0 += comb[k*68+lane];
            s1 += comb[k*68+32+lane];
            dd += comb[k*68+64];
            if(lane<3) cc2 += comb[k*68+65+lane];
        }
        float d = dd + 1e-8f;
        float q0 = s0/d, q1 = s1/d;
        float ss = warpSum(q0*q0 + q1*q1);
        float inv = 1.f / fmaxf(sqrtf(ss), 1e-8f);
        pr[(size_t)(v*NP+p)*64 + lane]      = q0*inv;
        pr[(size_t)(v*NP+p)*64 + 32 + lane] = q1*inv;
        if(lane<3) cp[(v*NP+p)*3 + lane] = cc2/d;
    }
    __syncthreads();
}

__device__ __forceinline__ void loss_phase(
    float* dyn, const float* __restrict__ jt,
    const float* __restrict__ se0, const float* __restrict__ sc0,
    const float* __restrict__ se1, const float* __restrict__ sc1,
    const float* __restrict__ cp,  const float* __restrict__ pr,
    const float* __restrict__ tg)
{
    float* spT  = dyn;               // 64*PS
    float* scpx = spT + 64*PS;       // 160
    float* scpy = scpx + 160;
    float* scpz = scpy + 160;
    float* taw  = scpz + 160;        // 12  (w axis values)
    float* tah  = taw + 12;          // 12  (h axis values)
    float* tad  = tah + 12;          // 16  (d axis values)
    __shared__ float bacc[2];

    int tid = threadIdx.x, lane = tid&31, wid = tid>>5;
    int v  = blockIdx.x / (NT/16);
    int m0 = (blockIdx.x - v*(NT/16))*16;

    stage_protos(spT, pr, v);
    for(int i=tid; i<160; i+=TPB){
        float x=0.f, yv=0.f, z=0.f;
        if(i<NP){ x=cp[(v*NP+i)*3+0]; yv=cp[(v*NP+i)*3+1]; z=cp[(v*NP+i)*3+2]; }
        scpx[i]=x; scpy[i]=yv; scpz[i]=z;
    }
    // teacher axis coordinates (identical expressions to the sampler)
    {
        float tzj = (jt[v*3+0]-0.5f)*2.f*(2.f/32.f);
        float tyj = (jt[v*3+1]-0.5f)*2.f*(8.f/96.f);
        float txj = (jt[v*3+2]-0.5f)*2.f*(8.f/96.f);
        if(tid < 16){
            float gz = ((float)tid + 0.5f)*2.f/16.f - 1.f + tzj;
            tad[tid] = unnorm_reflect(gz, (float)ID);
        }
        if(tid >= 32 && tid < 44){
            int i = tid - 32;
            float gy = ((float)i + 0.5f)*2.f/12.f - 1.f + tyj;
            tah[i] = unnorm_reflect(gy, (float)IH);
        }
        if(tid >= 64 && tid < 76){
            int i = tid - 64;
            float gx = ((float)i + 0.5f)*2.f/12.f - 1.f + txj;
            taw[i] = unnorm_reflect(gx, (float)IW);
        }
    }

    for(int sidx=0; sidx<2; sidx++){
        const float* se  = sidx ? se1 : se0;
        const float* scc = sidx ? sc1 : sc0;
        if(tid < 2) bacc[tid] = 0.f;
        __syncthreads();

        size_t gmb = (size_t)v*NT + m0 + wid*2;
        // s0 = channel0 = h-coord; s1 = channel1 = w-coord; s2 = channel2 = d-coord
        float r[2][2], s0[2], s1[2], s2[2];
        #pragma unroll
        for(int q=0;q<2;q++){
            r[0][q] = se[(gmb+q)*64 + lane];
            r[1][q] = se[(gmb+q)*64 + 32 + lane];
            s0[q] = scc[(gmb+q)*3+0]; s1[q] = scc[(gmb+q)*3+1]; s2[q] = scc[(gmb+q)*3+2];
        }

        // separable analytic argmin: channel0<->h axis, channel1<->w axis, channel2<->d axis
        float best[2]; int bi[2];
        #pragma unroll
        for(int q=0;q<2;q++){
            float mh = 1e30f; int ih = 0;
            #pragma unroll
            for(int i=0;i<12;i++){
                float d = s0[q]-tah[i]; float t = d*d;
                if(t < mh){ mh = t; ih = i; }
            }
            float mw = 1e30f; int iw2 = 0;
            #pragma unroll
            for(int i=0;i<12;i++){
                float d = s1[q]-taw[i]; float t = d*d;
                if(t < mw){ mw = t; iw2 = i; }
            }
            float md = 1e30f; int id2 = 0;
            #pragma unroll
            for(int i=0;i<16;i++){
                float d = (s2[q]-tad[i])*2.f; float t = d*d;
                if(t < md){ md = t; id2 = i; }
            }
            best[q] = mh + (mw + md);
            bi[q]   = (id2*12 + ih)*12 + iw2;   // flatten order: d-major, then h, then w
        }

        float acc[2][5];
        dot2(spT, lane, r, acc);

        bool v4 = lane < 16;
        #pragma unroll
        for(int q=0;q<2;q++){
            float lg[5], mx = -1e30f;
            #pragma unroll
            for(int j=0;j<5;j++){
                lg[j] = acc[q][j]*(1.f/0.03f);
                if(j<4 || v4) mx = fmaxf(mx, lg[j]);
            }
            mx = warpMax(mx);
            float sum = 0.f;
            #pragma unroll
            for(int j=0;j<5;j++) sum += (j<4||v4) ? expf(lg[j]-mx) : 0.f;
            sum = warpSum(sum);
            float lse = mx + logf(sum);

            const float* tgrow = tg + ((size_t)v*NT + bi[q])*NP;
            float ts = 0.f, ctr = 0.f;
            #pragma unroll
            for(int j=0;j<5;j++){
                if(j==4 && !v4) continue;
                int p = lane + 32*j;
                float dx = s0[q]-scpx[p];
                float dy = s1[q]-scpy[p];
                float dz = (s2[q]-scpz[p])*2.f;
                float pos = (expf(-(dx*dx+dy*dy+dz*dz)*INV2SIG2) >= 0.5f) ? 1.f : 0.f;
                float t = tgrow[p]*pos;
                ts  += t;
                ctr += t*(lg[j]-lse);
            }
            ts  = warpSum(ts);
            ctr = warpSum(ctr);
            if(lane==0 && sqrtf(best[q]) <= 3.0f){
                atomicAdd(&bacc[0], -ctr/(ts + 1e-8f));
                atomicAdd(&bacc[1], 1.f);
            }
        }
        __syncthreads();
        if(tid==0){
            atomicAdd(&g_acc[sidx*2+0], bacc[0]);
            atomicAdd(&g_acc[sidx*2+1], bacc[1]);
        }
        __syncthreads();
    }
}

__global__ void __launch_bounds__(TPB, 2)
fused_em_kernel(float* __restrict__ out, const float* __restrict__ jt)
{
    extern __shared__ float dyn[];

    if(blockIdx.x == 0 && threadIdx.x < 4) g_acc[threadIdx.x] = 0.f;

    for(int it=0; it<3; it++){
        assign_phase(dyn, g_tembn, g_ct, g_protos, g_cp, g_w, 1);
        grid_barrier();
        update_phase(dyn, g_w, g_temb, g_ct, g_part);
        grid_barrier();
        normalize_phase(dyn, g_part, g_protos, g_cp);
        grid_barrier();
    }
    assign_phase(dyn, g_tembn, g_ct, g_protos, g_cp, g_tgt, 0);
    grid_barrier();
    loss_phase(dyn, jt, g_s0e, g_s0c, g_s1e, g_s1c, g_cp, g_protos, g_tgt);
    grid_barrier();

    if(blockIdx.x == 0 && threadIdx.x == 0){
        out[0] = 0.5f*( g_acc[0]/(g_acc[1] + 1e-8f) + g_acc[2]/(g_acc[3] + 1e-8f) );
    }
}

// ---------------- host launch ----------------
extern "C" void kernel_launch(void* const* d_in, const int* in_sizes, int n_in,
                              void* d_out, int out_size)
{
    const float* e0  = (const float*)d_in[0];
    const float* e1  = (const float*)d_in[1];
    const float* et  = (const float*)d_in[2];
    const float* jp  = (const float*)d_in[7];
    const float* j0  = (const float*)d_in[8];
    const float* j1  = (const float*)d_in[9];
    const float* jt  = (const float*)d_in[10];

    float *protos,*cp,*temb,*tembn,*ct,*s0e,*s0c,*s1e,*s1c;
    cudaGetSymbolAddress((void**)&protos, g_protos);
    cudaGetSymbolAddress((void**)&cp,     g_cp);
    cudaGetSymbolAddress((void**)&temb,   g_temb);
    cudaGetSymbolAddress((void**)&tembn,  g_tembn);
    cudaGetSymbolAddress((void**)&ct,     g_ct);
    cudaGetSymbolAddress((void**)&s0e,    g_s0e);
    cudaGetSymbolAddress((void**)&s0c,    g_s0c);
    cudaGetSymbolAddress((void**)&s1e,    g_s1e);
    cudaGetSymbolAddress((void**)&s1c,    g_s1c);

    size_t fsm = (size_t)(NPER*16 + NPER*64 + NPER*3)*sizeof(float);   // 47808 B
    size_t alt = (size_t)(64*PS + 3*160 + 40)*sizeof(float);
    if(alt > fsm) fsm = alt;
    cudaFuncSetAttribute(fused_em_kernel, cudaFuncAttributeMaxDynamicSharedMemorySize, (int)fsm);

    SampleArgs a;
    a.emb[0]=et;  a.emb[1]=e0;  a.emb[2]=e1;
    a.jit[0]=jt;  a.jit[1]=j0;  a.jit[2]=j1;
    a.outn[0]=tembn; a.outn[1]=s0e; a.outn[2]=s1e;
    a.outraw[0]=temb; a.outraw[1]=nullptr; a.outraw[2]=nullptr;
    a.outc[0]=ct; a.outc[1]=s0c; a.outc[2]=s1c;
    a.pemb=et; a.pjit=jp; a.pout=protos; a.pcoord=cp;
    sample_all_kernel<<<dim3(NB*NT/4, 4), 256>>>(a);

    fused_em_kernel<<<NBLK, TPB, fsm>>>((float*)d_out, jt);
}

// round 7
// speedup vs baseline: 6.4939x; 1.0664x over previous
#include <cuda_runtime.h>
#include <math.h>

#define NB 2
#define CC 64
#define NP 144
#define NT 2304
#define IH 96
#define IW 96
#define ID 32
#define VOLSZ (IH*IW*ID)
#define NCHUNK 16
#define NPER   (NT/NCHUNK)   // 144
#define NBLK 288
#define TPB 256

#define INV2SIG2 ((float)(1.0/(2.0*(128.0/2.355)*(128.0/2.355))))

typedef unsigned long long ull;

// ---------------- scratch ----------------
__device__ float g_protos[NB*NP*CC];
__device__ float g_cp[NB*NP*3];
__device__ float g_temb [NB*NT*CC];
__device__ float g_tembn[NB*NT*CC];
__device__ float g_ct[NB*NT*3];
__device__ float g_s0e[NB*NT*CC];
__device__ float g_s0c[NB*NT*3];
__device__ float g_s1e[NB*NT*CC];
__device__ float g_s1c[NB*NT*3];
__device__ float g_w  [NB*NT*NP];
__device__ float g_tgt[NB*NT*NP];
__device__ float g_part[NCHUNK*NB*NP*68];
__device__ float g_acc[4];
__device__ unsigned g_bar_count = 0;
__device__ unsigned g_bar_gen   = 0;

// ---------------- packed f32x2 helpers ----------------
__device__ __forceinline__ ull packf2(float x, float y){
    ull r; asm("mov.b64 %0, {%1, %2};" : "=l"(r) : "f"(x), "f"(y)); return r;
}
__device__ __forceinline__ void unpackf2(ull v, float& x, float& y){
    asm("mov.b64 {%0, %1}, %2;" : "=f"(x), "=f"(y) : "l"(v));
}
__device__ __forceinline__ ull fma2(ull a, ull b, ull c){
    ull d; asm("fma.rn.f32x2 %0, %1, %2, %3;" : "=l"(d) : "l"(a), "l"(b), "l"(c)); return d;
}

// ---------------- grid barrier ----------------
__device__ __forceinline__ void grid_barrier(){
    __syncthreads();
    if(threadIdx.x == 0){
        __threadfence();
        unsigned gen = *((volatile unsigned*)&g_bar_gen);
        if(atomicAdd(&g_bar_count, 1u) == NBLK - 1u){
            atomicExch(&g_bar_count, 0u);
            __threadfence();
            atomicExch(&g_bar_gen, gen + 1u);
        } else {
            while(*((volatile unsigned*)&g_bar_gen) == gen){ __nanosleep(32); }
        }
        __threadfence();
    }
    __syncthreads();
}

// ---------------- helpers ----------------
__device__ __forceinline__ float unnorm_reflect(float c, float size){
    float x = ((c + 1.f)*size - 1.f)*0.5f;
    float xr = fabsf(x + 0.5f);
    float extra = fmodf(xr, size);
    float flips = floorf(xr / size);
    float r = (fmodf(flips, 2.f) == 0.f) ? extra : (size - extra);
    r -= 0.5f;
    return fminf(fmaxf(r, 0.f), size - 1.f);
}
__device__ __forceinline__ float warpMax(float x){
    #pragma unroll
    for(int o=16;o;o>>=1) x = fmaxf(x, __shfl_xor_sync(0xffffffffu, x, o));
    return x;
}
__device__ __forceinline__ float warpSum(float x){
    #pragma unroll
    for(int o=16;o;o>>=1) x += __shfl_xor_sync(0xffffffffu, x, o);
    return x;
}

__device__ __forceinline__ void trilerp_setup2(
    int x, int y, int z, int Dr, int Hr, int Wr,
    float tx, float ty, float tz,
    int xi[2], int yi[2], int zi[2], float wx[2], float wy[2], float wz[2],
    float* ux_o, float* uy_o, float* uz_o)
{
    float gx = ((float)x + 0.5f)*2.f/(float)Wr - 1.f + tx;
    float gy = ((float)y + 0.5f)*2.f/(float)Hr - 1.f + ty;
    float gz = ((float)z + 0.5f)*2.f/(float)Dr - 1.f + tz;
    float ux = unnorm_reflect(gx, (float)IW);
    float uy = unnorm_reflect(gy, (float)IH);
    float uz = unnorm_reflect(gz, (float)ID);
    float x0f = floorf(ux), y0f = floorf(uy), z0f = floorf(uz);
    float fx = ux-x0f, fy = uy-y0f, fz = uz-z0f;
    int x0=(int)x0f, y0=(int)y0f, z0=(int)z0f;
    xi[0]=min(max(x0,0),IW-1);  xi[1]=min(max(x0+1,0),IW-1);
    yi[0]=min(max(y0,0),IH-1);  yi[1]=min(max(y0+1,0),IH-1);
    zi[0]=min(max(z0,0),ID-1);  zi[1]=min(max(z0+1,0),ID-1);
    wx[0]=1.f-fx; wx[1]=fx; wy[0]=1.f-fy; wy[1]=fy; wz[0]=1.f-fz; wz[1]=fz;
    *ux_o=ux; *uy_o=uy; *uz_o=uz;
}

__device__ __forceinline__ float gather8(const float* __restrict__ base,
    const int xi[2], const int yi[2], const int zi[2],
    const float wx[2], const float wy[2], const float wz[2])
{
    float val = 0.f;
    #pragma unroll
    for(int dz=0; dz<2; dz++)
      #pragma unroll
      for(int dy=0; dy<2; dy++)
        #pragma unroll
        for(int dx=0; dx<2; dx++)
            val += wx[dx]*wy[dy]*wz[dz] *
                   base[((size_t)yi[dy]*IW + xi[dx])*ID + zi[dz]];
    return val;
}

// ---------------- coalesced sampling: grid (288, 4), 256 thr ----------------
struct SampleArgs {
    const float* emb[3]; const float* jit[3];
    float* outn[3]; float* outraw[3]; float* outc[3];
    const float* pemb; const float* pjit;
    float* pout; float* pcoord;
};

__global__ void sample_all_kernel(SampleArgs a)
{
    __shared__ float tile[16*68];
    __shared__ float ssqw[8*16];
    __shared__ float invn[16];
    __shared__ float uzs[16];
    __shared__ float pssq[64];

    int s = blockIdx.y;
    int tid = threadIdx.x;

    if(s == 3){
        // proto sampling: one point per block (288 blocks = NB*NP)
        int v = blockIdx.x / NP;
        int n = blockIdx.x - v*NP;
        const int Dr=4, Hr=6, Wr=6;
        int z = n/(Hr*Wr); int rem = n - z*(Hr*Wr); int yy = rem/Wr; int xx = rem - yy*Wr;
        const float* jit = a.pjit;
        float tz = (jit[v*3+0]-0.5f)*2.f*(8.f/32.f);
        float ty = (jit[v*3+1]-0.5f)*2.f*(16.f/96.f);
        float tx = (jit[v*3+2]-0.5f)*2.f*(16.f/96.f);
        int xi[2],yi[2],zi[2]; float wx[2],wy[2],wz[2],ux,uy,uz;
        trilerp_setup2(xx,yy,z,Dr,Hr,Wr,tx,ty,tz,xi,yi,zi,wx,wy,wz,&ux,&uy,&uz);
        int c = tid;
        float val = 0.f;
        if(c < 64) val = gather8(a.pemb + (size_t)(v*CC+c)*VOLSZ, xi,yi,zi,wx,wy,wz);
        if(c < 64) pssq[c] = val*val;
        __syncthreads();
        if(c<32) pssq[c]+=pssq[c+32]; __syncthreads();
        if(c<16) pssq[c]+=pssq[c+16]; __syncthreads();
        if(c< 8) pssq[c]+=pssq[c+ 8]; __syncthreads();
        if(c< 4) pssq[c]+=pssq[c+ 4]; __syncthreads();
        if(c< 2) pssq[c]+=pssq[c+ 2]; __syncthreads();
        if(c< 1) pssq[c]+=pssq[c+ 1]; __syncthreads();
        float inv = 1.f / fmaxf(sqrtf(pssq[0]), 1e-8f);
        if(c < 64) a.pout[(size_t)(v*NP+n)*CC + c] = val*inv;
        if(c == 0){
            float* oc = a.pcoord + (size_t)(v*NP+n)*3;
            oc[0] = uy; oc[1] = ux; oc[2] = uz;
        }
        return;
    }

    // big streams: block = (v, y, x); warps shuffle-gather d-rows
    int v  = blockIdx.x / 144;
    int yx = blockIdx.x - v*144;
    int yy = yx / 12, xx = yx - yy*12;
    const float* jit = a.jit[s];
    float tz = (jit[v*3+0]-0.5f)*2.f*(2.f/32.f);
    float ty = (jit[v*3+1]-0.5f)*2.f*(8.f/96.f);
    float tx = (jit[v*3+2]-0.5f)*2.f*(8.f/96.f);

    float gy = ((float)yy+0.5f)*(2.f/12.f) - 1.f + ty;
    float gx = ((float)xx+0.5f)*(2.f/12.f) - 1.f + tx;
    float uy = unnorm_reflect(gy, (float)IH);
    float ux = unnorm_reflect(gx, (float)IW);
    float y0f = floorf(uy), x0f = floorf(ux);
    float fy = uy-y0f, fx = ux-x0f;
    int y0 = (int)y0f, x0 = (int)x0f;
    int yi0 = min(max(y0,0),IH-1), yi1 = min(max(y0+1,0),IH-1);
    int xi0 = min(max(x0,0),IW-1), xi1 = min(max(x0+1,0),IW-1);
    int coff[4]; float wyx[4];
    coff[0]=(yi0*IW+xi0)*ID; wyx[0]=(1.f-fy)*(1.f-fx);
    coff[1]=(yi0*IW+xi1)*ID; wyx[1]=(1.f-fy)*fx;
    coff[2]=(yi1*IW+xi0)*ID; wyx[2]=fy*(1.f-fx);
    coff[3]=(yi1*IW+xi1)*ID; wyx[3]=fy*fx;

    int lane = tid & 31, warp = tid >> 5;
    int z = lane & 15;
    float gz = ((float)z+0.5f)*(2.f/16.f) - 1.f + tz;
    float uz = unnorm_reflect(gz, (float)ID);
    float z0f2 = floorf(uz); float fz = uz - z0f2; int zz0 = (int)z0f2;
    int zi0 = min(max(zz0,0),ID-1), zi1 = min(max(zz0+1,0),ID-1);
    float wz0 = 1.f-fz, wz1 = fz;
    if(tid < 16) uzs[tid] = uz;

    const float* emb = a.emb[s];
    size_t vbase = (size_t)v*CC*VOLSZ;

    float ssqacc = 0.f;
    #pragma unroll
    for(int pass=0; pass<8; pass++){
        int c = warp*8 + pass;
        const float* bc = emb + vbase + (size_t)c*VOLSZ;
        float r0 = bc[coff[0] + lane];
        float r1 = bc[coff[1] + lane];
        float r2 = bc[coff[2] + lane];
        float r3 = bc[coff[3] + lane];
        float v0 = wz0*__shfl_sync(0xffffffffu, r0, zi0) + wz1*__shfl_sync(0xffffffffu, r0, zi1);
        float v1 = wz0*__shfl_sync(0xffffffffu, r1, zi0) + wz1*__shfl_sync(0xffffffffu, r1, zi1);
        float v2 = wz0*__shfl_sync(0xffffffffu, r2, zi0) + wz1*__shfl_sync(0xffffffffu, r2, zi1);
        float v3 = wz0*__shfl_sync(0xffffffffu, r3, zi0) + wz1*__shfl_sync(0xffffffffu, r3, zi1);
        float val = wyx[0]*v0 + wyx[1]*v1 + wyx[2]*v2 + wyx[3]*v3;
        if(lane < 16){
            tile[z*68 + c] = val;
            ssqacc += val*val;
        }
    }
    if(lane < 16) ssqw[warp*16 + z] = ssqacc;
    __syncthreads();
    if(tid < 16){
        float ss = 0.f;
        #pragma unroll
        for(int w2=0; w2<8; w2++) ss += ssqw[w2*16+tid];
        invn[tid] = 1.f / fmaxf(sqrtf(ss), 1e-8f);
    }
    __syncthreads();

    int zo = tid >> 4, c4 = (tid & 15)*4;
    float4 tv = *(float4*)&tile[zo*68 + c4];
    int n = (zo*12 + yy)*12 + xx;
    size_t ob = ((size_t)v*NT + n)*64 + c4;
    float iv = invn[zo];
    float4 ov = make_float4(tv.x*iv, tv.y*iv, tv.z*iv, tv.w*iv);
    *(float4*)&a.outn[s][ob] = ov;
    if(a.outraw[s]) *(float4*)&a.outraw[s][ob] = tv;
    if(tid < 16){
        int n2 = (tid*12 + yy)*12 + xx;
        float* oc = a.outc[s] + ((size_t)v*NT + n2)*3;
        oc[0] = uy; oc[1] = ux; oc[2] = uzs[tid];
    }
}

// ================= fused EM + loss persistent kernel =================
// 288 blocks x 256 threads; dyn smem = 47808 bytes.
// proto smem layout (packed): spT2[32 chan-pairs][160 protos] of float2.

__device__ __forceinline__ void stage_protos2(float2* spT2, const float* __restrict__ pr, int v){
    int tid = threadIdx.x;
    const float4* src = (const float4*)(pr + (size_t)v*NP*CC);
    for(int i4 = tid; i4 < NP*CC/4; i4 += TPB){
        float4 q = src[i4];
        int i = i4*4;
        int p = i>>6, c0 = i&63;
        spT2[(c0>>1)*160 + p]       = make_float2(q.x, q.y);
        spT2[((c0>>1)+1)*160 + p]   = make_float2(q.z, q.w);
    }
    for(int i=tid; i<32*16; i+=TPB){
        int cc2 = i>>4, p = NP + (i&15);
        spT2[cc2*160 + p] = make_float2(0.f, 0.f);
    }
}

// packed dot: r[q] = float2 per lane (channels 2*lane, 2*lane+1) of point q
__device__ __forceinline__ void dot2p(const float2* __restrict__ spT2, int lane,
                                      const float2 r[2], float acc[2][5]){
    ull a[2][5];
    #pragma unroll
    for(int q=0;q<2;q++)
        #pragma unroll
        for(int j=0;j<5;j++) a[q][j]=0ULL;
    #pragma unroll 8
    for(int cc2=0; cc2<32; cc2++){
        const float2* row = spT2 + cc2*160 + lane;
        float2 p0=row[0], p1=row[32], p2=row[64], p3=row[96], p4=row[128];
        ull P0=*(ull*)&p0, P1=*(ull*)&p1, P2=*(ull*)&p2, P3=*(ull*)&p3, P4=*(ull*)&p4;
        #pragma unroll
        for(int q=0;q<2;q++){
            float ax = __shfl_sync(0xffffffffu, r[q].x, cc2);
            float ay = __shfl_sync(0xffffffffu, r[q].y, cc2);
            ull va = packf2(ax, ay);
            a[q][0]=fma2(va,P0,a[q][0]);
            a[q][1]=fma2(va,P1,a[q][1]);
            a[q][2]=fma2(va,P2,a[q][2]);
            a[q][3]=fma2(va,P3,a[q][3]);
            a[q][4]=fma2(va,P4,a[q][4]);
        }
    }
    #pragma unroll
    for(int q=0;q<2;q++)
        #pragma unroll
        for(int j=0;j<5;j++){
            float lo, hi; unpackf2(a[q][j], lo, hi);
            acc[q][j] = lo + hi;
        }
}

__device__ __forceinline__ void assign_phase(
    float* dyn, const float* __restrict__ tn, const float* __restrict__ ct,
    const float* __restrict__ pr, const float* __restrict__ cp,
    float* __restrict__ out, int useGauss)
{
    float2* spT2 = (float2*)dyn;          // 32*160 float2 = 10240 floats
    float* scpx = dyn + 10240;            // 160
    float* scpy = scpx + 160;
    float* scpz = scpy + 160;

    int tid = threadIdx.x, lane = tid&31, wid = tid>>5;
    int v  = blockIdx.x / (NT/16);
    int n0 = (blockIdx.x - v*(NT/16))*16;

    stage_protos2(spT2, pr, v);
    for(int i=tid; i<160; i+=TPB){
        float x=0.f, yv=0.f, zv=0.f;
        if(i<NP){ x=cp[(v*NP+i)*3+0]; yv=cp[(v*NP+i)*3+1]; zv=cp[(v*NP+i)*3+2]; }
        scpx[i]=x; scpy[i]=yv; scpz[i]=zv;
    }
    __syncthreads();

    size_t gnb = (size_t)v*NT + n0 + wid*2;
    float2 r[2]; float px[2], py[2], pz[2];
    #pragma unroll
    for(int q=0;q<2;q++){
        r[q] = ((const float2*)&tn[(gnb+q)*64])[lane];
        px[q] = ct[(gnb+q)*3+0]; py[q] = ct[(gnb+q)*3+1]; pz[q] = ct[(gnb+q)*3+2];
    }

    float acc[2][5];
    dot2p(spT2, lane, r, acc);

    bool v4 = lane < 16;
    #pragma unroll
    for(int q=0;q<2;q++){
        float lg[5], mx = -1e30f;
        #pragma unroll
        for(int j=0;j<5;j++){
            lg[j] = acc[q][j]*(1.f/0.015f);
            if(j<4 || v4) mx = fmaxf(mx, lg[j]);
        }
        mx = warpMax(mx);
        float e[5], sum = 0.f;
        #pragma unroll
        for(int j=0;j<5;j++){ e[j] = (j<4||v4) ? expf(lg[j]-mx) : 0.f; sum += e[j]; }
        sum = warpSum(sum);
        float invs = 1.f/sum;
        #pragma unroll
        for(int j=0;j<5;j++){
            if(j==4 && !v4) continue;
            int p = lane + 32*j;
            float aa = e[j]*invs;
            if(useGauss){
                float dx = px[q]-scpx[p];
                float dy = py[q]-scpy[p];
                float dz = (pz[q]-scpz[p])*2.f;
                aa *= expf(-(dx*dx+dy*dy+dz*dz)*INV2SIG2);
            }
            out[(gnb+q)*NP + p] = aa;
        }
    }
}

__device__ __forceinline__ void update_phase(
    float* dyn, const float* __restrict__ w, const float* __restrict__ temb,
    const float* __restrict__ ct, float* __restrict__ part)
{
    float* sw_ = dyn;             // NPER*16
    float* st  = sw_ + NPER*16;   // NPER*64
    float* sc  = st + NPER*64;    // NPER*3

    int tid = threadIdx.x, lane = tid&31, wp = tid>>5;
    int bx = blockIdx.x;
    int v  = bx / (9*NCHUNK);
    int rr = bx - v*(9*NCHUNK);
    int ch = rr / 9, pblk = rr - ch*9;
    int p0b = pblk*16;
    size_t gn0 = (size_t)v*NT + ch*NPER;

    for(int i=tid; i<NPER*16; i+=TPB){
        int n = i>>4, pj = i&15;
        sw_[i] = w[(gn0+n)*NP + p0b + pj];
    }
    {
        const float4* src = (const float4*)(temb + gn0*64);
        float4* dst = (float4*)st;
        for(int i=tid; i<NPER*16; i+=TPB) dst[i] = src[i];
    }
    for(int i=tid; i<NPER*3; i+=TPB) sc[i] = ct[gn0*3 + i];
    __syncthreads();

    // warp handles protos p0b + wp*2 + {0,1}; lane holds channels (2*lane, 2*lane+1)
    ull ap[2] = {0ULL, 0ULL};
    float dn[2] = {0.f, 0.f}, ca[2] = {0.f, 0.f};
    #pragma unroll 4
    for(int n=0;n<NPER;n++){
        float2 wv = ((const float2*)&sw_[n*16])[wp];
        float2 tv = ((const float2*)&st[n*64])[lane];
        ull tvp = *(ull*)&tv;
        ull w0p = packf2(wv.x, wv.x);
        ull w1p = packf2(wv.y, wv.y);
        ap[0] = fma2(w0p, tvp, ap[0]);
        ap[1] = fma2(w1p, tvp, ap[1]);
        dn[0] += wv.x; dn[1] += wv.y;
        if(lane<3){ float cv = sc[n*3+lane]; ca[0] = fmaf(wv.x,cv,ca[0]); ca[1] = fmaf(wv.y,cv,ca[1]); }
    }
    #pragma unroll
    for(int j=0;j<2;j++){
        int p = p0b + wp*2 + j;
        size_t b0 = ((size_t)(ch*NB + v)*NP + p)*68;
        float lo, hi; unpackf2(ap[j], lo, hi);
        part[b0 + 2*lane]     = lo;
        part[b0 + 2*lane + 1] = hi;
        if(lane==0) part[b0+64] = dn[j];
        if(lane<3)  part[b0+65+lane] = ca[j];
    }
}

__device__ __forceinline__ void normalize_phase(
    float* dyn, const float* __restrict__ part,
    float* __restrict__ pr, float* __restrict__ cp)
{
    float* comb = dyn;   // 8*68
    int lane = threadIdx.x & 31, wid = threadIdx.x >> 5;
    int b = blockIdx.x;
    int v = b / NP, p = b - v*NP;

    float a0=0.f, a1=0.f, den=0.f, ca=0.f;
    #pragma unroll
    for(int k=0;k<2;k++){
        int ch = wid + 8*k;
        size_t bb = ((size_t)(ch*NB + v)*NP + p)*68;
        float2 q2 = *(const float2*)&part[bb + 2*lane];
        a0  += q2.x;
        a1  += q2.y;
        den += part[bb+64];
        if(lane<3) ca += part[bb+65+lane];
    }
    comb[wid*68 + 2*lane]     = a0;
    comb[wid*68 + 2*lane + 1] = a1;
    if(lane==0) comb[wid*68+64] = den;
    if(lane<3)  comb[wid*68+65+lane] = ca;
    __syncthreads();
    if(wid==0){
        float s0=0.f, s1=0.f, dd=0.f, cc2=0.f;
        #pragma unroll
        for(int k=0;k<8;k++){
            s0 += comb[k*68 + 2*lane];
            s1 += comb[k*68 + 2*lane + 1];
            dd += comb[k*68+64];
            if(lane<3) cc2 += comb[k*68+65+lane];
        }
        float d = dd + 1e-8f;
        float q0 = s0/d, q1 = s1/d;
        float ss = warpSum(q0*q0 + q1*q1);
        float inv = 1.f / fmaxf(sqrtf(ss), 1e-8f);
        float2 o2 = make_float2(q0*inv, q1*inv);
        *(float2*)&pr[(size_t)(v*NP+p)*64 + 2*lane] = o2;
        if(lane<3) cp[(v*NP+p)*3 + lane] = cc2/d;
    }
    __syncthreads();
}

__device__ __forceinline__ void loss_phase(
    float* dyn, const float* __restrict__ jt,
    const float* __restrict__ se0, const float* __restrict__ sc0,
    const float* __restrict__ se1, const float* __restrict__ sc1,
    const float* __restrict__ cp,  const float* __restrict__ pr,
    const float* __restrict__ tg)
{
    float2* spT2 = (float2*)dyn;          // 10240 floats
    float* scpx = dyn + 10240;            // 160
    float* scpy = scpx + 160;
    float* scpz = scpy + 160;
    float* taw  = scpz + 160;             // 12
    float* tah  = taw + 12;               // 12
    float* tad  = tah + 12;               // 16
    __shared__ float bacc[2];

    int tid = threadIdx.x, lane = tid&31, wid = tid>>5;
    int v  = blockIdx.x / (NT/16);
    int m0 = (blockIdx.x - v*(NT/16))*16;

    stage_protos2(spT2, pr, v);
    for(int i=tid; i<160; i+=TPB){
        float x=0.f, yv=0.f, zv=0.f;
        if(i<NP){ x=cp[(v*NP+i)*3+0]; yv=cp[(v*NP+i)*3+1]; zv=cp[(v*NP+i)*3+2]; }
        scpx[i]=x; scpy[i]=yv; scpz[i]=zv;
    }
    {
        float tzj = (jt[v*3+0]-0.5f)*2.f*(2.f/32.f);
        float tyj = (jt[v*3+1]-0.5f)*2.f*(8.f/96.f);
        float txj = (jt[v*3+2]-0.5f)*2.f*(8.f/96.f);
        if(tid < 16){
            float gz = ((float)tid + 0.5f)*2.f/16.f - 1.f + tzj;
            tad[tid] = unnorm_reflect(gz, (float)ID);
        }
        if(tid >= 32 && tid < 44){
            int i = tid - 32;
            float gy = ((float)i + 0.5f)*2.f/12.f - 1.f + tyj;
            tah[i] = unnorm_reflect(gy, (float)IH);
        }
        if(tid >= 64 && tid < 76){
            int i = tid - 64;
            float gx = ((float)i + 0.5f)*2.f/12.f - 1.f + txj;
            taw[i] = unnorm_reflect(gx, (float)IW);
        }
    }

    for(int sidx=0; sidx<2; sidx++){
        const float* se  = sidx ? se1 : se0;
        const float* scc = sidx ? sc1 : sc0;
        if(tid < 2) bacc[tid] = 0.f;
        __syncthreads();

        size_t gmb = (size_t)v*NT + m0 + wid*2;
        float2 r[2]; float s0[2], s1[2], s2[2];
        #pragma unroll
        for(int q=0;q<2;q++){
            r[q] = ((const float2*)&se[(gmb+q)*64])[lane];
            s0[q] = scc[(gmb+q)*3+0]; s1[q] = scc[(gmb+q)*3+1]; s2[q] = scc[(gmb+q)*3+2];
        }

        // separable analytic argmin: ch0<->h, ch1<->w, ch2<->d
        float best[2]; int bi[2];
        #pragma unroll
        for(int q=0;q<2;q++){
            float mh = 1e30f; int ih = 0;
            #pragma unroll
            for(int i=0;i<12;i++){
                float d = s0[q]-tah[i]; float t = d*d;
                if(t < mh){ mh = t; ih = i; }
            }
            float mw = 1e30f; int iw2 = 0;
            #pragma unroll
            for(int i=0;i<12;i++){
                float d = s1[q]-taw[i]; float t = d*d;
                if(t < mw){ mw = t; iw2 = i; }
            }
            float md = 1e30f; int id2 = 0;
            #pragma unroll
            for(int i=0;i<16;i++){
                float d = (s2[q]-tad[i])*2.f; float t = d*d;
                if(t < md){ md = t; id2 = i; }
            }
            best[q] = mh + (mw + md);
            bi[q]   = (id2*12 + ih)*12 + iw2;
        }

        float acc[2][5];
        dot2p(spT2, lane, r, acc);

        bool v4 = lane < 16;
        #pragma unroll
        for(int q=0;q<2;q++){
            float lg[5], mx = -1e30f;
            #pragma unroll
            for(int j=0;j<5;j++){
                lg[j] = acc[q][j]*(1.f/0.03f);
                if(j<4 || v4) mx = fmaxf(mx, lg[j]);
            }
            mx = warpMax(mx);
            float sum = 0.f;
            #pragma unroll
            for(int j=0;j<5;j++) sum += (j<4||v4) ? expf(lg[j]-mx) : 0.f;
            sum = warpSum(sum);
            float lse = mx + logf(sum);

            const float* tgrow = tg + ((size_t)v*NT + bi[q])*NP;
            float ts = 0.f, ctr = 0.f;
            #pragma unroll
            for(int j=0;j<5;j++){
                if(j==4 && !v4) continue;
                int p = lane + 32*j;
                float dx = s0[q]-scpx[p];
                float dy = s1[q]-scpy[p];
                float dz = (s2[q]-scpz[p])*2.f;
                float pos = (expf(-(dx*dx+dy*dy+dz*dz)*INV2SIG2) >= 0.5f) ? 1.f : 0.f;
                float t = tgrow[p]*pos;
                ts  += t;
                ctr += t*(lg[j]-lse);
            }
            ts  = warpSum(ts);
            ctr = warpSum(ctr);
            if(lane==0 && sqrtf(best[q]) <= 3.0f){
                atomicAdd(&bacc[0], -ctr/(ts + 1e-8f));
                atomicAdd(&bacc[1], 1.f);
            }
        }
        __syncthreads();
        if(tid==0){
            atomicAdd(&g_acc[sidx*2+0], bacc[0]);
            atomicAdd(&g_acc[sidx*2+1], bacc[1]);
        }
        __syncthreads();
    }
}

__global__ void __launch_bounds__(TPB, 2)
fused_em_kernel(float* __restrict__ out, const float* __restrict__ jt)
{
    extern __shared__ float dyn[];

    if(blockIdx.x == 0 && threadIdx.x < 4) g_acc[threadIdx.x] = 0.f;

    for(int it=0; it<3; it++){
        assign_phase(dyn, g_tembn, g_ct, g_protos, g_cp, g_w, 1);
        grid_barrier();
        update_phase(dyn, g_w, g_temb, g_ct, g_part);
        grid_barrier();
        normalize_phase(dyn, g_part, g_protos, g_cp);
        grid_barrier();
    }
    assign_phase(dyn, g_tembn, g_ct, g_protos, g_cp, g_tgt, 0);
    grid_barrier();
    loss_phase(dyn, jt, g_s0e, g_s0c, g_s1e, g_s1c, g_cp, g_protos, g_tgt);
    grid_barrier();

    if(blockIdx.x == 0 && threadIdx.x == 0){
        out[0] = 0.5f*( g_acc[0]/(g_acc[1] + 1e-8f) + g_acc[2]/(g_acc[3] + 1e-8f) );
    }
}

// ---------------- host launch ----------------
extern "C" void kernel_launch(void* const* d_in, const int* in_sizes, int n_in,
                              void* d_out, int out_size)
{
    const float* e0  = (const float*)d_in[0];
    const float* e1  = (const float*)d_in[1];
    const float* et  = (const float*)d_in[2];
    const float* jp  = (const float*)d_in[7];
    const float* j0  = (const float*)d_in[8];
    const float* j1  = (const float*)d_in[9];
    const float* jt  = (const float*)d_in[10];

    float *protos,*cp,*temb,*tembn,*ct,*s0e,*s0c,*s1e,*s1c;
    cudaGetSymbolAddress((void**)&protos, g_protos);
    cudaGetSymbolAddress((void**)&cp,     g_cp);
    cudaGetSymbolAddress((void**)&temb,   g_temb);
    cudaGetSymbolAddress((void**)&tembn,  g_tembn);
    cudaGetSymbolAddress((void**)&ct,     g_ct);
    cudaGetSymbolAddress((void**)&s0e,    g_s0e);
    cudaGetSymbolAddress((void**)&s0c,    g_s0c);
    cudaGetSymbolAddress((void**)&s1e,    g_s1e);
    cudaGetSymbolAddress((void**)&s1c,    g_s1c);

    // dyn smem: update = NPER*83 floats (47808 B) dominates; assign/loss = 43200 B
    size_t fsm = (size_t)(NPER*16 + NPER*64 + NPER*3)*sizeof(float);
    size_t alt = (size_t)(10240 + 3*160 + 40)*sizeof(float);
    if(alt > fsm) fsm = alt;
    cudaFuncSetAttribute(fused_em_kernel, cudaFuncAttributeMaxDynamicSharedMemorySize, (int)fsm);

    SampleArgs a;
    a.emb[0]=et;  a.emb[1]=e0;  a.emb[2]=e1;
    a.jit[0]=jt;  a.jit[1]=j0;  a.jit[2]=j1;
    a.outn[0]=tembn; a.outn[1]=s0e; a.outn[2]=s1e;
    a.outraw[0]=temb; a.outraw[1]=nullptr; a.outraw[2]=nullptr;
    a.outc[0]=ct; a.outc[1]=s0c; a.outc[2]=s1c;
    a.pemb=et; a.pjit=jp; a.pout=protos; a.pcoord=cp;
    sample_all_kernel<<<dim3(288, 4), 256>>>(a);

    fused_em_kernel<<<NBLK, TPB, fsm>>>((float*)d_out, jt);
}

// round 8
// speedup vs baseline: 7.1099x; 1.0949x over previous
#include <cuda_runtime.h>
#include <math.h>

#define NB 2
#define CC 64
#define NP 144
#define NT 2304
#define IH 96
#define IW 96
#define ID 32
#define VOLSZ (IH*IW*ID)
#define NCHUNK 16
#define NPER   (NT/NCHUNK)   // 144
#define PS 161               // padded stride of transposed proto smem [cc][p]
#define NBLK 288
#define TPB 256

#define INV2SIG2 ((float)(1.0/(2.0*(128.0/2.355)*(128.0/2.355))))

// ---------------- scratch ----------------
__device__ float g_protos[NB*NP*CC];
__device__ float g_cp[NB*NP*3];
__device__ float g_temb [NB*NT*CC];
__device__ float g_tembn[NB*NT*CC];
__device__ float g_ct[NB*NT*3];
__device__ float g_s0e[NB*NT*CC];
__device__ float g_s0c[NB*NT*3];
__device__ float g_s1e[NB*NT*CC];
__device__ float g_s1c[NB*NT*3];
__device__ float g_w  [NB*NT*NP];
__device__ float g_tgt[NB*NT*NP];
__device__ float g_part[NCHUNK*NB*NP*68];
__device__ float g_acc[4];
__device__ unsigned g_flags[NBLK];
__device__ unsigned g_release;

// ---------------- flag-array grid barrier (monotonic, replay-safe) ----------------
__device__ __forceinline__ void grid_barrier(unsigned tgt){
    __syncthreads();
    if(blockIdx.x == 0){
        if(threadIdx.x == 0){
            __threadfence();
            *((volatile unsigned*)&g_flags[0]) = tgt;
        }
        for(int i = threadIdx.x; i < NBLK; i += TPB){
            while(*((volatile unsigned*)&g_flags[i]) < tgt){}
        }
        __threadfence();
        __syncthreads();
        if(threadIdx.x == 0){
            *((volatile unsigned*)&g_release) = tgt;
        }
    } else {
        if(threadIdx.x == 0){
            __threadfence();
            *((volatile unsigned*)&g_flags[blockIdx.x]) = tgt;
            while(*((volatile unsigned*)&g_release) < tgt){}
            __threadfence();
        }
        __syncthreads();
    }
}

// ---------------- helpers ----------------
__device__ __forceinline__ float unnorm_reflect(float c, float size){
    float x = ((c + 1.f)*size - 1.f)*0.5f;
    float xr = fabsf(x + 0.5f);
    float extra = fmodf(xr, size);
    float flips = floorf(xr / size);
    float r = (fmodf(flips, 2.f) == 0.f) ? extra : (size - extra);
    r -= 0.5f;
    return fminf(fmaxf(r, 0.f), size - 1.f);
}
__device__ __forceinline__ float warpMax(float x){
    #pragma unroll
    for(int o=16;o;o>>=1) x = fmaxf(x, __shfl_xor_sync(0xffffffffu, x, o));
    return x;
}
__device__ __forceinline__ float warpSum(float x){
    #pragma unroll
    for(int o=16;o;o>>=1) x += __shfl_xor_sync(0xffffffffu, x, o);
    return x;
}

__device__ __forceinline__ void trilerp_setup2(
    int x, int y, int z, int Dr, int Hr, int Wr,
    float tx, float ty, float tz,
    int xi[2], int yi[2], int zi[2], float wx[2], float wy[2], float wz[2],
    float* ux_o, float* uy_o, float* uz_o)
{
    float gx = ((float)x + 0.5f)*2.f/(float)Wr - 1.f + tx;
    float gy = ((float)y + 0.5f)*2.f/(float)Hr - 1.f + ty;
    float gz = ((float)z + 0.5f)*2.f/(float)Dr - 1.f + tz;
    float ux = unnorm_reflect(gx, (float)IW);
    float uy = unnorm_reflect(gy, (float)IH);
    float uz = unnorm_reflect(gz, (float)ID);
    float x0f = floorf(ux), y0f = floorf(uy), z0f = floorf(uz);
    float fx = ux-x0f, fy = uy-y0f, fz = uz-z0f;
    int x0=(int)x0f, y0=(int)y0f, z0=(int)z0f;
    xi[0]=min(max(x0,0),IW-1);  xi[1]=min(max(x0+1,0),IW-1);
    yi[0]=min(max(y0,0),IH-1);  yi[1]=min(max(y0+1,0),IH-1);
    zi[0]=min(max(z0,0),ID-1);  zi[1]=min(max(z0+1,0),ID-1);
    wx[0]=1.f-fx; wx[1]=fx; wy[0]=1.f-fy; wy[1]=fy; wz[0]=1.f-fz; wz[1]=fz;
    *ux_o=ux; *uy_o=uy; *uz_o=uz;
}

__device__ __forceinline__ float gather8(const float* __restrict__ base,
    const int xi[2], const int yi[2], const int zi[2],
    const float wx[2], const float wy[2], const float wz[2])
{
    float val = 0.f;
    #pragma unroll
    for(int dz=0; dz<2; dz++)
      #pragma unroll
      for(int dy=0; dy<2; dy++)
        #pragma unroll
        for(int dx=0; dx<2; dx++)
            val += wx[dx]*wy[dy]*wz[dz] *
                   base[((size_t)yi[dy]*IW + xi[dx])*ID + zi[dz]];
    return val;
}

// ---------------- coalesced sampling: grid (288, 4), 256 thr ----------------
struct SampleArgs {
    const float* emb[3]; const float* jit[3];
    float* outn[3]; float* outraw[3]; float* outc[3];
    const float* pemb; const float* pjit;
    float* pout; float* pcoord;
};

__global__ void sample_all_kernel(SampleArgs a)
{
    __shared__ float tile[16*68];
    __shared__ float ssqw[8*16];
    __shared__ float invn[16];
    __shared__ float uzs[16];
    __shared__ float pssq[64];

    int s = blockIdx.y;
    int tid = threadIdx.x;

    if(s == 3){
        int v = blockIdx.x / NP;
        int n = blockIdx.x - v*NP;
        const int Dr=4, Hr=6, Wr=6;
        int z = n/(Hr*Wr); int rem = n - z*(Hr*Wr); int yy = rem/Wr; int xx = rem - yy*Wr;
        const float* jit = a.pjit;
        float tz = (jit[v*3+0]-0.5f)*2.f*(8.f/32.f);
        float ty = (jit[v*3+1]-0.5f)*2.f*(16.f/96.f);
        float tx = (jit[v*3+2]-0.5f)*2.f*(16.f/96.f);
        int xi[2],yi[2],zi[2]; float wx[2],wy[2],wz[2],ux,uy,uz;
        trilerp_setup2(xx,yy,z,Dr,Hr,Wr,tx,ty,tz,xi,yi,zi,wx,wy,wz,&ux,&uy,&uz);
        int c = tid;
        float val = 0.f;
        if(c < 64) val = gather8(a.pemb + (size_t)(v*CC+c)*VOLSZ, xi,yi,zi,wx,wy,wz);
        if(c < 64) pssq[c] = val*val;
        __syncthreads();
        if(c<32) pssq[c]+=pssq[c+32]; __syncthreads();
        if(c<16) pssq[c]+=pssq[c+16]; __syncthreads();
        if(c< 8) pssq[c]+=pssq[c+ 8]; __syncthreads();
        if(c< 4) pssq[c]+=pssq[c+ 4]; __syncthreads();
        if(c< 2) pssq[c]+=pssq[c+ 2]; __syncthreads();
        if(c< 1) pssq[c]+=pssq[c+ 1]; __syncthreads();
        float inv = 1.f / fmaxf(sqrtf(pssq[0]), 1e-8f);
        if(c < 64) a.pout[(size_t)(v*NP+n)*CC + c] = val*inv;
        if(c == 0){
            float* oc = a.pcoord + (size_t)(v*NP+n)*3;
            oc[0] = uy; oc[1] = ux; oc[2] = uz;
        }
        return;
    }

    int v  = blockIdx.x / 144;
    int yx = blockIdx.x - v*144;
    int yy = yx / 12, xx = yx - yy*12;
    const float* jit = a.jit[s];
    float tz = (jit[v*3+0]-0.5f)*2.f*(2.f/32.f);
    float ty = (jit[v*3+1]-0.5f)*2.f*(8.f/96.f);
    float tx = (jit[v*3+2]-0.5f)*2.f*(8.f/96.f);

    float gy = ((float)yy+0.5f)*(2.f/12.f) - 1.f + ty;
    float gx = ((float)xx+0.5f)*(2.f/12.f) - 1.f + tx;
    float uy = unnorm_reflect(gy, (float)IH);
    float ux = unnorm_reflect(gx, (float)IW);
    float y0f = floorf(uy), x0f = floorf(ux);
    float fy = uy-y0f, fx = ux-x0f;
    int y0 = (int)y0f, x0 = (int)x0f;
    int yi0 = min(max(y0,0),IH-1), yi1 = min(max(y0+1,0),IH-1);
    int xi0 = min(max(x0,0),IW-1), xi1 = min(max(x0+1,0),IW-1);
    int coff[4]; float wyx[4];
    coff[0]=(yi0*IW+xi0)*ID; wyx[0]=(1.f-fy)*(1.f-fx);
    coff[1]=(yi0*IW+xi1)*ID; wyx[1]=(1.f-fy)*fx;
    coff[2]=(yi1*IW+xi0)*ID; wyx[2]=fy*(1.f-fx);
    coff[3]=(yi1*IW+xi1)*ID; wyx[3]=fy*fx;

    int lane = tid & 31, warp = tid >> 5;
    int z = lane & 15;
    float gz = ((float)z+0.5f)*(2.f/16.f) - 1.f + tz;
    float uz = unnorm_reflect(gz, (float)ID);
    float z0f2 = floorf(uz); float fz = uz - z0f2; int zz0 = (int)z0f2;
    int zi0 = min(max(zz0,0),ID-1), zi1 = min(max(zz0+1,0),ID-1);
    float wz0 = 1.f-fz, wz1 = fz;
    if(tid < 16) uzs[tid] = uz;

    const float* emb = a.emb[s];
    size_t vbase = (size_t)v*CC*VOLSZ;

    float ssqacc = 0.f;
    #pragma unroll
    for(int pass=0; pass<8; pass++){
        int c = warp*8 + pass;
        const float* bc = emb + vbase + (size_t)c*VOLSZ;
        float r0 = bc[coff[0] + lane];
        float r1 = bc[coff[1] + lane];
        float r2 = bc[coff[2] + lane];
        float r3 = bc[coff[3] + lane];
        float v0 = wz0*__shfl_sync(0xffffffffu, r0, zi0) + wz1*__shfl_sync(0xffffffffu, r0, zi1);
        float v1 = wz0*__shfl_sync(0xffffffffu, r1, zi0) + wz1*__shfl_sync(0xffffffffu, r1, zi1);
        float v2 = wz0*__shfl_sync(0xffffffffu, r2, zi0) + wz1*__shfl_sync(0xffffffffu, r2, zi1);
        float v3 = wz0*__shfl_sync(0xffffffffu, r3, zi0) + wz1*__shfl_sync(0xffffffffu, r3, zi1);
        float val = wyx[0]*v0 + wyx[1]*v1 + wyx[2]*v2 + wyx[3]*v3;
        if(lane < 16){
            tile[z*68 + c] = val;
            ssqacc += val*val;
        }
    }
    if(lane < 16) ssqw[warp*16 + z] = ssqacc;
    __syncthreads();
    if(tid < 16){
        float ss = 0.f;
        #pragma unroll
        for(int w2=0; w2<8; w2++) ss += ssqw[w2*16+tid];
        invn[tid] = 1.f / fmaxf(sqrtf(ss), 1e-8f);
    }
    __syncthreads();

    int zo = tid >> 4, c4 = (tid & 15)*4;
    float4 tv = *(float4*)&tile[zo*68 + c4];
    int n = (zo*12 + yy)*12 + xx;
    size_t ob = ((size_t)v*NT + n)*64 + c4;
    float iv = invn[zo];
    float4 ov = make_float4(tv.x*iv, tv.y*iv, tv.z*iv, tv.w*iv);
    *(float4*)&a.outn[s][ob] = ov;
    if(a.outraw[s]) *(float4*)&a.outraw[s][ob] = tv;
    if(tid < 16){
        int n2 = (tid*12 + yy)*12 + xx;
        float* oc = a.outc[s] + ((size_t)v*NT + n2)*3;
        oc[0] = uy; oc[1] = ux; oc[2] = uzs[tid];
    }
}

// ================= fused EM + loss persistent kernel =================

__device__ __forceinline__ void stage_protos(float* spT, const float* __restrict__ pr, int v){
    int tid = threadIdx.x;
    const float4* src = (const float4*)(pr + (size_t)v*NP*CC);
    for(int i4 = tid; i4 < NP*CC/4; i4 += TPB){
        float4 q = src[i4];
        int i = i4*4;
        int p = i>>6, c0 = i&63;
        spT[(c0+0)*PS + p] = q.x;
        spT[(c0+1)*PS + p] = q.y;
        spT[(c0+2)*PS + p] = q.z;
        spT[(c0+3)*PS + p] = q.w;
    }
    for(int i=tid; i<64*(PS-NP); i+=TPB){
        int cc2 = i/(PS-NP), p = NP + i%(PS-NP);
        spT[cc2*PS + p] = 0.f;
    }
}

__device__ __forceinline__ void dot2(const float* __restrict__ spT, int lane,
                                     const float r[2][2], float acc[2][5]){
    #pragma unroll
    for(int q=0;q<2;q++)
        #pragma unroll
        for(int j=0;j<5;j++) acc[q][j]=0.f;
    #pragma unroll
    for(int h=0;h<2;h++){
        #pragma unroll 8
        for(int cc2=0; cc2<32; cc2++){
            const float* row = spT + (h*32+cc2)*PS + lane;
            float p0=row[0], p1=row[32], p2=row[64], p3=row[96], p4=row[128];
            #pragma unroll
            for(int q=0;q<2;q++){
                float vv = __shfl_sync(0xffffffffu, r[h][q], cc2);
                acc[q][0]=fmaf(vv,p0,acc[q][0]);
                acc[q][1]=fmaf(vv,p1,acc[q][1]);
                acc[q][2]=fmaf(vv,p2,acc[q][2]);
                acc[q][3]=fmaf(vv,p3,acc[q][3]);
                acc[q][4]=fmaf(vv,p4,acc[q][4]);
            }
        }
    }
}

__device__ __forceinline__ void assign_phase(
    float* dyn, const float* __restrict__ tn, const float* __restrict__ ct,
    const float* __restrict__ pr, const float* __restrict__ cp,
    float* __restrict__ out, int useGauss)
{
    float* spT  = dyn;            // 64*PS
    float* scpx = spT + 64*PS;    // 160
    float* scpy = scpx + 160;
    float* scpz = scpy + 160;

    int tid = threadIdx.x, lane = tid&31, wid = tid>>5;
    int v  = blockIdx.x / (NT/16);
    int n0 = (blockIdx.x - v*(NT/16))*16;

    stage_protos(spT, pr, v);
    for(int i=tid; i<160; i+=TPB){
        float x=0.f, yv=0.f, z=0.f;
        if(i<NP){ x=cp[(v*NP+i)*3+0]; yv=cp[(v*NP+i)*3+1]; z=cp[(v*NP+i)*3+2]; }
        scpx[i]=x; scpy[i]=yv; scpz[i]=z;
    }
    __syncthreads();

    size_t gnb = (size_t)v*NT + n0 + wid*2;
    float r[2][2], px[2], py[2], pz[2];
    #pragma unroll
    for(int q=0;q<2;q++){
        r[0][q] = tn[(gnb+q)*64 + lane];
        r[1][q] = tn[(gnb+q)*64 + 32 + lane];
        px[q] = ct[(gnb+q)*3+0]; py[q] = ct[(gnb+q)*3+1]; pz[q] = ct[(gnb+q)*3+2];
    }

    float acc[2][5];
    dot2(spT, lane, r, acc);

    bool v4 = lane < 16;
    #pragma unroll
    for(int q=0;q<2;q++){
        float lg[5], mx = -1e30f;
        #pragma unroll
        for(int j=0;j<5;j++){
            lg[j] = acc[q][j]*(1.f/0.015f);
            if(j<4 || v4) mx = fmaxf(mx, lg[j]);
        }
        mx = warpMax(mx);
        float e[5], sum = 0.f;
        #pragma unroll
        for(int j=0;j<5;j++){ e[j] = (j<4||v4) ? expf(lg[j]-mx) : 0.f; sum += e[j]; }
        sum = warpSum(sum);
        float invs = 1.f/sum;
        #pragma unroll
        for(int j=0;j<5;j++){
            if(j==4 && !v4) continue;
            int p = lane + 32*j;
            float aa = e[j]*invs;
            if(useGauss){
                float dx = px[q]-scpx[p];
                float dy = py[q]-scpy[p];
                float dz = (pz[q]-scpz[p])*2.f;
                aa *= expf(-(dx*dx+dy*dy+dz*dz)*INV2SIG2);
            }
            out[(gnb+q)*NP + p] = aa;
        }
    }
}

__device__ __forceinline__ void update_phase(
    float* dyn, const float* __restrict__ w, const float* __restrict__ temb,
    const float* __restrict__ ct, float* __restrict__ part)
{
    float* sw_ = dyn;             // NPER*16
    float* st  = sw_ + NPER*16;   // NPER*64
    float* sc  = st + NPER*64;    // NPER*3

    int tid = threadIdx.x, lane = tid&31, wp = tid>>5;
    int bx = blockIdx.x;
    int v  = bx / (9*NCHUNK);
    int rr = bx - v*(9*NCHUNK);
    int ch = rr / 9, pblk = rr - ch*9;
    int p0b = pblk*16;
    size_t gn0 = (size_t)v*NT + ch*NPER;

    for(int i=tid; i<NPER*16; i+=TPB){
        int n = i>>4, pj = i&15;
        sw_[i] = w[(gn0+n)*NP + p0b + pj];
    }
    {
        const float4* src = (const float4*)(temb + gn0*64);
        float4* dst = (float4*)st;
        for(int i=tid; i<NPER*16; i+=TPB) dst[i] = src[i];
    }
    for(int i=tid; i<NPER*3; i+=TPB) sc[i] = ct[gn0*3 + i];
    __syncthreads();

    float a0[2]={0.f,0.f}, a1[2]={0.f,0.f}, dn[2]={0.f,0.f}, ca[2]={0.f,0.f};
    #pragma unroll 4
    for(int n=0;n<NPER;n++){
        float2 wv = *(const float2*)&sw_[n*16 + wp*2];
        float t0 = st[n*64+lane], t1 = st[n*64+32+lane];
        float cv = (lane<3) ? sc[n*3+lane] : 0.f;
        a0[0] = fmaf(wv.x,t0,a0[0]); a1[0] = fmaf(wv.x,t1,a1[0]);
        a0[1] = fmaf(wv.y,t0,a0[1]); a1[1] = fmaf(wv.y,t1,a1[1]);
        dn[0] += wv.x; dn[1] += wv.y;
        ca[0] = fmaf(wv.x,cv,ca[0]); ca[1] = fmaf(wv.y,cv,ca[1]);
    }
    #pragma unroll
    for(int j=0;j<2;j++){
        int p = p0b + wp*2 + j;
        size_t b0 = ((size_t)(ch*NB + v)*NP + p)*68;
        part[b0+lane]    = a0[j];
        part[b0+32+lane] = a1[j];
        if(lane==0) part[b0+64] = dn[j];
        if(lane<3)  part[b0+65+lane] = ca[j];
    }
}

__device__ __forceinline__ void normalize_phase(
    float* dyn, const float* __restrict__ part,
    float* __restrict__ pr, float* __restrict__ cp)
{
    float* comb = dyn;   // 8*68
    int lane = threadIdx.x & 31, wid = threadIdx.x >> 5;
    int b = blockIdx.x;
    int v = b / NP, p = b - v*NP;

    float a0=0.f, a1=0.f, den=0.f, ca=0.f;
    #pragma unroll
    for(int k=0;k<2;k++){
        int ch = wid + 8*k;
        size_t bb = ((size_t)(ch*NB + v)*NP + p)*68;
        a0  += part[bb+lane];
        a1  += part[bb+32+lane];
        den += part[bb+64];
        if(lane<3) ca += part[bb+65+lane];
    }
    comb[wid*68+lane]    = a0;
    comb[wid*68+32+lane] = a1;
    if(lane==0) comb[wid*68+64] = den;
    if(lane<3)  comb[wid*68+65+lane] = ca;
    __syncthreads();
    if(wid==0){
        float s0=0.f, s1=0.f, dd=0.f, cc2=0.f;
        #pragma unroll
        for(int k=0;k<8;k++){
            s0 += comb[k*68+lane];
            s1 += comb[k*68+32+lane];
            dd += comb[k*68+64];
            if(lane<3) cc2 += comb[k*68+65+lane];
        }
        float d = dd + 1e-8f;
        float q0 = s0/d, q1 = s1/d;
        float ss = warpSum(q0*q0 + q1*q1);
        float inv = 1.f / fmaxf(sqrtf(ss), 1e-8f);
        pr[(size_t)(v*NP+p)*64 + lane]      = q0*inv;
        pr[(size_t)(v*NP+p)*64 + 32 + lane] = q1*inv;
        if(lane<3) cp[(v*NP+p)*3 + lane] = cc2/d;
    }
    __syncthreads();
}

__device__ __forceinline__ void loss_phase(
    float* dyn, const float* __restrict__ jt,
    const float* __restrict__ se0, const float* __restrict__ sc0,
    const float* __restrict__ se1, const float* __restrict__ sc1,
    const float* __restrict__ cp,  const float* __restrict__ pr,
    const float* __restrict__ tg)
{
    float* spT  = dyn;               // 64*PS
    float* scpx = spT + 64*PS;       // 160
    float* scpy = scpx + 160;
    float* scpz = scpy + 160;
    float* taw  = scpz + 160;        // 12
    float* tah  = taw + 12;          // 12
    float* tad  = tah + 12;          // 16
    __shared__ float bacc[2];

    int tid = threadIdx.x, lane = tid&31, wid = tid>>5;
    int v  = blockIdx.x / (NT/16);
    int m0 = (blockIdx.x - v*(NT/16))*16;

    stage_protos(spT, pr, v);
    for(int i=tid; i<160; i+=TPB){
        float x=0.f, yv=0.f, z=0.f;
        if(i<NP){ x=cp[(v*NP+i)*3+0]; yv=cp[(v*NP+i)*3+1]; z=cp[(v*NP+i)*3+2]; }
        scpx[i]=x; scpy[i]=yv; scpz[i]=z;
    }
    {
        float tzj = (jt[v*3+0]-0.5f)*2.f*(2.f/32.f);
        float tyj = (jt[v*3+1]-0.5f)*2.f*(8.f/96.f);
        float txj = (jt[v*3+2]-0.5f)*2.f*(8.f/96.f);
        if(tid < 16){
            float gz = ((float)tid + 0.5f)*2.f/16.f - 1.f + tzj;
            tad[tid] = unnorm_reflect(gz, (float)ID);
        }
        if(tid >= 32 && tid < 44){
            int i = tid - 32;
            float gy = ((float)i + 0.5f)*2.f/12.f - 1.f + tyj;
            tah[i] = unnorm_reflect(gy, (float)IH);
        }
        if(tid >= 64 && tid < 76){
            int i = tid - 64;
            float gx = ((float)i + 0.5f)*2.f/12.f - 1.f + txj;
            taw[i] = unnorm_reflect(gx, (float)IW);
        }
    }

    for(int sidx=0; sidx<2; sidx++){
        const float* se  = sidx ? se1 : se0;
        const float* scc = sidx ? sc1 : sc0;
        if(tid < 2) bacc[tid] = 0.f;
        __syncthreads();

        size_t gmb = (size_t)v*NT + m0 + wid*2;
        float r[2][2], s0[2], s1[2], s2[2];
        #pragma unroll
        for(int q=0;q<2;q++){
            r[0][q] = se[(gmb+q)*64 + lane];
            r[1][q] = se[(gmb+q)*64 + 32 + lane];
            s0[q] = scc[(gmb+q)*3+0]; s1[q] = scc[(gmb+q)*3+1]; s2[q] = scc[(gmb+q)*3+2];
        }

        // separable analytic argmin: ch0<->h, ch1<->w, ch2<->d
        float best[2]; int bi[2];
        #pragma unroll
        for(int q=0;q<2;q++){
            float mh = 1e30f; int ih = 0;
            #pragma unroll
            for(int i=0;i<12;i++){
                float d = s0[q]-tah[i]; float t = d*d;
                if(t < mh){ mh = t; ih = i; }
            }
            float mw = 1e30f; int iw2 = 0;
            #pragma unroll
            for(int i=0;i<12;i++){
                float d = s1[q]-taw[i]; float t = d*d;
                if(t < mw){ mw = t; iw2 = i; }
            }
            float md = 1e30f; int id2 = 0;
            #pragma unroll
            for(int i=0;i<16;i++){
                float d = (s2[q]-tad[i])*2.f; float t = d*d;
                if(t < md){ md = t; id2 = i; }
            }
            best[q] = mh + (mw + md);
            bi[q]   = (id2*12 + ih)*12 + iw2;
        }

        float acc[2][5];
        dot2(spT, lane, r, acc);

        bool v4 = lane < 16;
        #pragma unroll
        for(int q=0;q<2;q++){
            float lg[5], mx = -1e30f;
            #pragma unroll
            for(int j=0;j<5;j++){
                lg[j] = acc[q][j]*(1.f/0.03f);
                if(j<4 || v4) mx = fmaxf(mx, lg[j]);
            }
            mx = warpMax(mx);
            float sum = 0.f;
            #pragma unroll
            for(int j=0;j<5;j++) sum += (j<4||v4) ? expf(lg[j]-mx) : 0.f;
            sum = warpSum(sum);
            float lse = mx + logf(sum);

            const float* tgrow = tg + ((size_t)v*NT + bi[q])*NP;
            float ts = 0.f, ctr = 0.f;
            #pragma unroll
            for(int j=0;j<5;j++){
                if(j==4 && !v4) continue;
                int p = lane + 32*j;
                float dx = s0[q]-scpx[p];
                float dy = s1[q]-scpy[p];
                float dz = (s2[q]-scpz[p])*2.f;
                float pos = (expf(-(dx*dx+dy*dy+dz*dz)*INV2SIG2) >= 0.5f) ? 1.f : 0.f;
                float t = tgrow[p]*pos;
                ts  += t;
                ctr += t*(lg[j]-lse);
            }
            ts  = warpSum(ts);
            ctr = warpSum(ctr);
            if(lane==0 && sqrtf(best[q]) <= 3.0f){
                atomicAdd(&bacc[0], -ctr/(ts + 1e-8f));
                atomicAdd(&bacc[1], 1.f);
            }
        }
        __syncthreads();
        if(tid==0){
            atomicAdd(&g_acc[sidx*2+0], bacc[0]);
            atomicAdd(&g_acc[sidx*2+1], bacc[1]);
        }
        __syncthreads();
    }
}

__global__ void __launch_bounds__(TPB, 2)
fused_em_kernel(float* __restrict__ out, const float* __restrict__ jt)
{
    extern __shared__ float dyn[];
    __shared__ unsigned s_base;

    if(threadIdx.x == 0) s_base = *((volatile unsigned*)&g_flags[blockIdx.x]);
    if(blockIdx.x == 0 && threadIdx.x < 4) g_acc[threadIdx.x] = 0.f;
    __syncthreads();
    unsigned base = s_base;
    unsigned k = 0;

    for(int it=0; it<3; it++){
        assign_phase(dyn, g_tembn, g_ct, g_protos, g_cp, g_w, 1);
        grid_barrier(base + ++k);
        update_phase(dyn, g_w, g_temb, g_ct, g_part);
        grid_barrier(base + ++k);
        normalize_phase(dyn, g_part, g_protos, g_cp);
        grid_barrier(base + ++k);
    }
    assign_phase(dyn, g_tembn, g_ct, g_protos, g_cp, g_tgt, 0);
    grid_barrier(base + ++k);
    loss_phase(dyn, jt, g_s0e, g_s0c, g_s1e, g_s1c, g_cp, g_protos, g_tgt);
    grid_barrier(base + ++k);

    if(blockIdx.x == 0 && threadIdx.x == 0){
        out[0] = 0.5f*( g_acc[0]/(g_acc[1] + 1e-8f) + g_acc[2]/(g_acc[3] + 1e-8f) );
    }
}

// ---------------- host launch ----------------
extern "C" void kernel_launch(void* const* d_in, const int* in_sizes, int n_in,
                              void* d_out, int out_size)
{
    const float* e0  = (const float*)d_in[0];
    const float* e1  = (const float*)d_in[1];
    const float* et  = (const float*)d_in[2];
    const float* jp  = (const float*)d_in[7];
    const float* j0  = (const float*)d_in[8];
    const float* j1  = (const float*)d_in[9];
    const float* jt  = (const float*)d_in[10];

    float *protos,*cp,*temb,*tembn,*ct,*s0e,*s0c,*s1e,*s1c;
    cudaGetSymbolAddress((void**)&protos, g_protos);
    cudaGetSymbolAddress((void**)&cp,     g_cp);
    cudaGetSymbolAddress((void**)&temb,   g_temb);
    cudaGetSymbolAddress((void**)&tembn,  g_tembn);
    cudaGetSymbolAddress((void**)&ct,     g_ct);
    cudaGetSymbolAddress((void**)&s0e,    g_s0e);
    cudaGetSymbolAddress((void**)&s0c,    g_s0c);
    cudaGetSymbolAddress((void**)&s1e,    g_s1e);
    cudaGetSymbolAddress((void**)&s1c,    g_s1c);

    size_t fsm = (size_t)(NPER*16 + NPER*64 + NPER*3)*sizeof(float);   // 47808 B
    size_t alt = (size_t)(64*PS + 3*160 + 40)*sizeof(float);
    if(alt > fsm) fsm = alt;
    cudaFuncSetAttribute(fused_em_kernel, cudaFuncAttributeMaxDynamicSharedMemorySize, (int)fsm);

    SampleArgs a;
    a.emb[0]=et;  a.emb[1]=e0;  a.emb[2]=e1;
    a.jit[0]=jt;  a.jit[1]=j0;  a.jit[2]=j1;
    a.outn[0]=tembn; a.outn[1]=s0e; a.outn[2]=s1e;
    a.outraw[0]=temb; a.outraw[1]=nullptr; a.outraw[2]=nullptr;
    a.outc[0]=ct; a.outc[1]=s0c; a.outc[2]=s1c;
    a.pemb=et; a.pjit=jp; a.pout=protos; a.pcoord=cp;
    sample_all_kernel<<<dim3(288, 4), 256>>>(a);

    fused_em_kernel<<<NBLK, TPB, fsm>>>((float*)d_out, jt);
}